// round 5
// baseline (speedup 1.0000x reference)
#include <cuda_runtime.h>
#include <cstdint>

#define BATCH 1024
#define NV 6890
#define KJ 24
#define NBETA 10
#define NPOSE 207
#define NPP 208          // 207 pose rows + 1 zero pad (=13*16)
#define NC 20670         // NV*3
#define NCHUNKS 13
#define NVSEG 864

// ---- scratch (device globals; no allocations allowed) ----
__device__ float g_JT0[KJ * 3];
__device__ float g_JS[KJ * 30];
__device__ float g_part[8 * KJ * 33];
__device__ float g_pfT[NPP * BATCH];      // pose feature transposed [p][b], row 207 = 0
__device__ float g_A[BATCH * KJ * 12];    // per batch/joint 3x4 [R|t]

// ---- output layout (concatenated tuple, float32) ----
#define OUT_JT   (BATCH * NV * 3)
#define OUT_J    (OUT_JT + BATCH * KJ * 3)
#define OUT_ROT  (OUT_J + BATCH * KJ * 3)

// ---- packed f32x2 helpers ----
typedef unsigned long long u64;
__device__ __forceinline__ u64 pk2(float lo, float hi) {
    u64 r; asm("mov.b64 %0, {%1, %2};" : "=l"(r) : "f"(lo), "f"(hi)); return r;
}
__device__ __forceinline__ void upk2(u64 v, float& lo, float& hi) {
    asm("mov.b64 {%0, %1}, %2;" : "=f"(lo), "=f"(hi) : "l"(v));
}
__device__ __forceinline__ u64 ff2(u64 a, u64 b, u64 c) {
    u64 d; asm("fma.rn.f32x2 %0, %1, %2, %3;" : "=l"(d) : "l"(a), "l"(b), "l"(c));
    return d;
}

// ---- cp.async helpers ----
__device__ __forceinline__ void cpa16(uint32_t dst, const void* src, int sb) {
    asm volatile("cp.async.cg.shared.global [%0], [%1], 16, %2;"
                 :: "r"(dst), "l"(src), "r"(sb));
}
__device__ __forceinline__ void cpa8(uint32_t dst, const void* src, int sb) {
    asm volatile("cp.async.ca.shared.global [%0], [%1], 8, %2;"
                 :: "r"(dst), "l"(src), "r"(sb));
}
__device__ __forceinline__ void cpcommit() {
    asm volatile("cp.async.commit_group;");
}

#define MMA_TF32(d, a, b) \
    asm volatile("mma.sync.aligned.m16n8k8.row.col.f32.tf32.tf32.f32 " \
        "{%0,%1,%2,%3}, {%4,%5,%6,%7}, {%8,%9}, {%0,%1,%2,%3};" \
        : "+f"(d[0]), "+f"(d[1]), "+f"(d[2]), "+f"(d[3]) \
        : "r"(a[0]), "r"(a[1]), "r"(a[2]), "r"(a[3]), "r"(b[0]), "r"(b[1]))

// ============================================================================
// Kernel 1a/1b: JT0 = Jreg @ v_template; JS = Jreg . shapedirs (split over V)
// ============================================================================
__global__ void k1a_jreduce(const float* __restrict__ Jreg,
                            const float* __restrict__ vt,
                            const float* __restrict__ sd)
{
    int k = blockIdx.x;
    int seg = blockIdx.y;
    int tid = threadIdx.x;
    int v0 = seg * NVSEG;
    int v1 = min(NV, v0 + NVSEG);
    float acc[33];
#pragma unroll
    for (int e = 0; e < 33; e++) acc[e] = 0.f;

    for (int v = v0 + tid; v < v1; v += 256) {
        float j = Jreg[k * NV + v];
        const float* vp = vt + v * 3;
        acc[0] = fmaf(j, vp[0], acc[0]);
        acc[1] = fmaf(j, vp[1], acc[1]);
        acc[2] = fmaf(j, vp[2], acc[2]);
        const float* sp = sd + v * 30;
#pragma unroll
        for (int e = 0; e < 30; e++) acc[3 + e] = fmaf(j, sp[e], acc[3 + e]);
    }
#pragma unroll
    for (int e = 0; e < 33; e++) {
        for (int off = 16; off; off >>= 1)
            acc[e] += __shfl_down_sync(0xffffffffu, acc[e], off);
    }
    __shared__ float red[8][33];
    int lane = tid & 31, w = tid >> 5;
    if (lane == 0) {
#pragma unroll
        for (int e = 0; e < 33; e++) red[w][e] = acc[e];
    }
    __syncthreads();
    if (tid < 33) {
        float s = 0.f;
#pragma unroll
        for (int w2 = 0; w2 < 8; w2++) s += red[w2][tid];
        g_part[(k * 8 + seg) * 33 + tid] = s;
    }
}

__global__ void k1b_combine()
{
    int idx = threadIdx.x;
    for (; idx < KJ * 33; idx += 256) {
        int k = idx / 33, e = idx % 33;
        float s = 0.f;
#pragma unroll
        for (int seg = 0; seg < 8; seg++) s += g_part[(k * 8 + seg) * 33 + e];
        if (e < 3) g_JT0[k * 3 + e] = s;
        else       g_JS[k * 30 + (e - 3)] = s;
    }
}

// ============================================================================
// Kernel 2: 8 batches/block, one warp per batch. Rodrigues, pose feature,
// joints_t, kinematic chain, A matrices.
// ============================================================================
__global__ __launch_bounds__(256) void k2_batch(
    const float* __restrict__ body_pose,
    const float* __restrict__ betas,
    const float* __restrict__ global_orient,
    const int* __restrict__ parents,
    float* __restrict__ out)
{
    int w = threadIdx.x >> 5;
    int t = threadIdx.x & 31;
    int b = blockIdx.x * 8 + w;
    __shared__ float Rm[8][KJ][9];
    __shared__ float jt[8][KJ][3];
    __shared__ float rel[8][KJ][3];
    __shared__ float ch[8][KJ][12];

    if (t < KJ) {
        float ax, ay, az;
        if (t == 0) {
            ax = global_orient[b * 3 + 0];
            ay = global_orient[b * 3 + 1];
            az = global_orient[b * 3 + 2];
        } else {
            const float* p = body_pose + b * 69 + (t - 1) * 3;
            ax = p[0]; ay = p[1]; az = p[2];
        }
        float ex = ax + 1e-8f, ey = ay + 1e-8f, ez = az + 1e-8f;
        float angle = sqrtf(ex * ex + ey * ey + ez * ez);
        float inv = 1.0f / angle;
        float ux = ax * inv, uy = ay * inv, uz = az * inv;
        float s = sinf(angle), c = cosf(angle);
        float oc = 1.0f - c;
        float uu = ux * ux + uy * uy + uz * uz;
        float r0 = 1.0f + oc * (ux * ux - uu);
        float r1 = -s * uz + oc * (ux * uy);
        float r2 =  s * uy + oc * (ux * uz);
        float r3 =  s * uz + oc * (uy * ux);
        float r4 = 1.0f + oc * (uy * uy - uu);
        float r5 = -s * ux + oc * (uy * uz);
        float r6 = -s * uy + oc * (uz * ux);
        float r7 =  s * ux + oc * (uz * uy);
        float r8 = 1.0f + oc * (uz * uz - uu);
        Rm[w][t][0] = r0; Rm[w][t][1] = r1; Rm[w][t][2] = r2;
        Rm[w][t][3] = r3; Rm[w][t][4] = r4; Rm[w][t][5] = r5;
        Rm[w][t][6] = r6; Rm[w][t][7] = r7; Rm[w][t][8] = r8;

        float* ro = out + OUT_ROT + (size_t)b * 216 + t * 9;
        ro[0] = r0; ro[1] = r1; ro[2] = r2; ro[3] = r3; ro[4] = r4;
        ro[5] = r5; ro[6] = r6; ro[7] = r7; ro[8] = r8;

        if (t >= 1) {
            int p0 = (t - 1) * 9;
            g_pfT[(p0 + 0) * BATCH + b] = r0 - 1.0f;
            g_pfT[(p0 + 1) * BATCH + b] = r1;
            g_pfT[(p0 + 2) * BATCH + b] = r2;
            g_pfT[(p0 + 3) * BATCH + b] = r3;
            g_pfT[(p0 + 4) * BATCH + b] = r4 - 1.0f;
            g_pfT[(p0 + 5) * BATCH + b] = r5;
            g_pfT[(p0 + 6) * BATCH + b] = r6;
            g_pfT[(p0 + 7) * BATCH + b] = r7;
            g_pfT[(p0 + 8) * BATCH + b] = r8 - 1.0f;
        } else {
            g_pfT[207 * BATCH + b] = 0.0f;   // pad row
        }

#pragma unroll
        for (int cc = 0; cc < 3; cc++) {
            float s2 = g_JT0[t * 3 + cc];
#pragma unroll
            for (int l = 0; l < NBETA; l++)
                s2 = fmaf(g_JS[t * 30 + cc * 10 + l], betas[b * 10 + l], s2);
            jt[w][t][cc] = s2;
            out[OUT_JT + (size_t)b * 72 + t * 3 + cc] = s2;
        }
    }
    __syncwarp();
    if (t < KJ) {
        if (t == 0) {
            rel[w][0][0] = jt[w][0][0]; rel[w][0][1] = jt[w][0][1]; rel[w][0][2] = jt[w][0][2];
        } else {
            int p = parents[t];
            rel[w][t][0] = jt[w][t][0] - jt[w][p][0];
            rel[w][t][1] = jt[w][t][1] - jt[w][p][1];
            rel[w][t][2] = jt[w][t][2] - jt[w][p][2];
        }
    }
    __syncwarp();
    if (t < 12) {
        int i = t >> 2, j = t & 3;
        ch[w][0][t] = (j < 3) ? Rm[w][0][i * 3 + j] : rel[w][0][i];
    }
    __syncwarp();
    for (int k = 1; k < KJ; k++) {
        int p = parents[k];
        if (t < 12) {
            int i = t >> 2, j = t & 3;
            float v;
            if (j < 3) {
                v = ch[w][p][i * 4 + 0] * Rm[w][k][0 * 3 + j]
                  + ch[w][p][i * 4 + 1] * Rm[w][k][1 * 3 + j]
                  + ch[w][p][i * 4 + 2] * Rm[w][k][2 * 3 + j];
            } else {
                v = ch[w][p][i * 4 + 0] * rel[w][k][0]
                  + ch[w][p][i * 4 + 1] * rel[w][k][1]
                  + ch[w][p][i * 4 + 2] * rel[w][k][2]
                  + ch[w][p][i * 4 + 3];
            }
            ch[w][k][t] = v;
        }
        __syncwarp();
    }
    if (t < KJ) {
        out[OUT_J + (size_t)b * 72 + t * 3 + 0] = ch[w][t][3];
        out[OUT_J + (size_t)b * 72 + t * 3 + 1] = ch[w][t][7];
        out[OUT_J + (size_t)b * 72 + t * 3 + 2] = ch[w][t][11];
        float* Ao = g_A + ((size_t)b * KJ + t) * 12;
#pragma unroll
        for (int i = 0; i < 3; i++) {
            float tr = ch[w][t][i * 4 + 3]
                     - (ch[w][t][i * 4 + 0] * jt[w][t][0]
                      + ch[w][t][i * 4 + 1] * jt[w][t][1]
                      + ch[w][t][i * 4 + 2] * jt[w][t][2]);
            Ao[i * 4 + 0] = ch[w][t][i * 4 + 0];
            Ao[i * 4 + 1] = ch[w][t][i * 4 + 1];
            Ao[i * 4 + 2] = ch[w][t][i * 4 + 2];
            Ao[i * 4 + 3] = tr;
        }
    }
}

// ============================================================================
// Kernel 3: tf32 mma.sync GEMM + fp32 shape + FFMA2 LBS.
// Block: 192 coords x 64 batches, 256 threads (8 warps, 4m x 2n).
// 4-stage cp.async ring, ONE barrier per chunk. 2 CTAs/SM.
// Epilogue: 1 batch x 16 vertices per thread, A from gmem (L1).
// ============================================================================
#define SF_STAGE 4352                 // A 16x200=3200 + B 16x72=1152
#define CS_STRIDE 65                  // Csm 192x65 = 12480 (aliases stages)
#define S_W     17408                 // 24*64 = 1536
#define S_SD    (S_W + 1536)          // 64*30 = 1920
#define S_VT    (S_SD + 1920)         // 192
#define S_BET   (S_VT + 192)          // 640
#define SMEM_FL (S_BET + 640)         // 21696
#define SMEM_BYTES (SMEM_FL * 4)      // 86784

__device__ __forceinline__ void k3_load_stage(uint32_t smb,
                                              const float* __restrict__ posedirs,
                                              int n0, int kc, int st, int tid)
{
#pragma unroll
    for (int j = 0; j < 6; j++) {
        int i = tid + j * 256;            // < 1536
        int row = i / 96, c2 = i % 96;
        int p = kc * 16 + row;
        int col = n0 + c2 * 2;
        int sb = 0;
        if (p < NPOSE) {
            int rem = NC - col;
            sb = (rem >= 2) ? 8 : 0;
        }
        const float* src = posedirs + (size_t)min(p, NPOSE - 1) * NC
                                    + (sb ? col : 0);
        cpa8(smb + (uint32_t)(st * SF_STAGE + row * 200 + c2 * 2) * 4, src, sb);
    }
    {
        int row = tid / 16, c4 = tid % 16;
        int p = kc * 16 + row;
        int bBase = blockIdx.x * 64;
        cpa16(smb + (uint32_t)(st * SF_STAGE + 3200 + row * 72 + c4 * 4) * 4,
              g_pfT + (size_t)p * BATCH + bBase + c4 * 4, 16);
    }
}

__global__ __launch_bounds__(256, 2) void k3_lbs(
    const float* __restrict__ posedirs,
    const float* __restrict__ lbs_w,
    const float* __restrict__ shapedirs,
    const float* __restrict__ v_template,
    const float* __restrict__ betas,
    float* __restrict__ out)
{
    extern __shared__ float sm[];
    uint32_t smb = (uint32_t)__cvta_generic_to_shared(sm);
    int tid = threadIdx.x;
    int lane = tid & 31, warp = tid >> 5;
    int bBase = blockIdx.x * 64;
    int n0 = blockIdx.y * 192;
    int v0 = n0 / 3;
    int mW = (warp & 3) * 48;
    int nW = (warp >> 2) * 32;

    // ---- epilogue tables via cp.async (group 0) ----
    {
        int validf = (NV - v0) * 30; if (validf > 1920) validf = 1920;
#pragma unroll
        for (int j = 0; j < 2; j++) {
            int i = tid + j * 256;
            if (i < 480) {
                int fo = i * 4;
                int rem = validf - fo;
                int sb = rem >= 4 ? 16 : (rem > 0 ? rem * 4 : 0);
                cpa16(smb + (uint32_t)(S_SD + fo) * 4,
                      shapedirs + (size_t)v0 * 30 + (sb ? fo : 0), sb);
            }
        }
        if (tid < 48) {
            int fo = tid * 4;
            int validv = (NV - v0) * 3; if (validv > 192) validv = 192;
            int rem = validv - fo;
            int sb = rem >= 4 ? 16 : (rem > 0 ? rem * 4 : 0);
            cpa16(smb + (uint32_t)(S_VT + fo) * 4,
                  v_template + (size_t)v0 * 3 + (sb ? fo : 0), sb);
        }
        if (tid < 160) {
            cpa16(smb + (uint32_t)(S_BET + tid * 4) * 4,
                  betas + (size_t)bBase * 10 + tid * 4, 16);
        }
    }
    cpcommit();

    // ---- prefetch GEMM chunks 0, 1 ----
    k3_load_stage(smb, posedirs, n0, 0, 0, tid); cpcommit();
    k3_load_stage(smb, posedirs, n0, 1, 1, tid); cpcommit();

    // ---- weights (transposed [k][64]) via plain loads ----
#pragma unroll
    for (int j = 0; j < 6; j++) {
        int i = tid + j * 256;
        int k = i >> 6, vl = i & 63;
        int vg = v0 + vl;
        sm[S_W + k * 64 + vl] = (vg < NV) ? lbs_w[vg * KJ + k] : 0.f;
    }

    float acc[3][4][4];
#pragma unroll
    for (int it = 0; it < 3; it++)
#pragma unroll
        for (int jt = 0; jt < 4; jt++)
#pragma unroll
            for (int e = 0; e < 4; e++) acc[it][jt][e] = 0.f;

    // ---- main k-loop: one barrier per chunk ----
    for (int kc = 0; kc < NCHUNKS; kc++) {
        if (kc + 2 < NCHUNKS)
            k3_load_stage(smb, posedirs, n0, kc + 2, (kc + 2) & 3, tid);
        cpcommit();
        asm volatile("cp.async.wait_group 2;");
        __syncthreads();

        const float* As = sm + (kc & 3) * SF_STAGE;
        const float* Bs = As + 3200;
#pragma unroll
        for (int kk = 0; kk < 2; kk++) {
            int k0 = kk * 8;
            uint32_t a[3][4], b[4][2];
            int ar0 = (k0 + (lane & 3)) * 200 + mW + (lane >> 2);
            int ar1 = ar0 + 4 * 200;
#pragma unroll
            for (int it = 0; it < 3; it++) {
                a[it][0] = __float_as_uint(As[ar0 + it * 16]);
                a[it][1] = __float_as_uint(As[ar0 + it * 16 + 8]);
                a[it][2] = __float_as_uint(As[ar1 + it * 16]);
                a[it][3] = __float_as_uint(As[ar1 + it * 16 + 8]);
            }
            int br0 = (k0 + (lane & 3)) * 72 + nW + (lane >> 2);
            int br1 = br0 + 4 * 72;
#pragma unroll
            for (int jt = 0; jt < 4; jt++) {
                b[jt][0] = __float_as_uint(Bs[br0 + jt * 8]);
                b[jt][1] = __float_as_uint(Bs[br1 + jt * 8]);
            }
#pragma unroll
            for (int it = 0; it < 3; it++)
#pragma unroll
                for (int jt = 0; jt < 4; jt++)
                    MMA_TF32(acc[it][jt], a[it], b[jt]);
        }
    }
    __syncthreads();   // all compute done before Csm overwrites stages

    // ---- dump accumulators to Csm (stage region is dead) ----
    {
        float* Cs = sm;
#pragma unroll
        for (int it = 0; it < 3; it++)
#pragma unroll
            for (int jt = 0; jt < 4; jt++) {
                int m = mW + it * 16 + (lane >> 2);
                int n = nW + jt * 8 + 2 * (lane & 3);
                Cs[m * CS_STRIDE + n]           = acc[it][jt][0];
                Cs[m * CS_STRIDE + n + 1]       = acc[it][jt][1];
                Cs[(m + 8) * CS_STRIDE + n]     = acc[it][jt][2];
                Cs[(m + 8) * CS_STRIDE + n + 1] = acc[it][jt][3];
            }
    }
    asm volatile("cp.async.wait_group 0;");
    __syncthreads();

    // ---- epilogue: 1 batch x 16 vertices per thread, 2 passes of 8 ----
    int tn = tid & 3;        // vertex group (16 v = 48 coords)
    int tb = tid >> 2;       // batch
    const float* Cs   = sm;
    const float* w_s  = sm + S_W;
    const float* sd_s = sm + S_SD;
    const float* vt_s = sm + S_VT;
    const float* bt_s = sm + S_BET;

    float bet[10];
#pragma unroll
    for (int l = 0; l < NBETA; l++) bet[l] = bt_s[tb * 10 + l];
    const float4* Abase = (const float4*)(g_A + (size_t)(bBase + tb) * 288);
    int gb = bBase + tb;

#pragma unroll
    for (int h2 = 0; h2 < 2; h2++) {
        // v_posed for 8 vertices (fp32 shape + template + GEMM result)
        float vpf[24];
#pragma unroll
        for (int vi = 0; vi < 8; vi++) {
            int vl = tn * 16 + h2 * 8 + vi;
#pragma unroll
            for (int c = 0; c < 3; c++) {
                float s = vt_s[vl * 3 + c];
#pragma unroll
                for (int l = 0; l < NBETA; l++)
                    s = fmaf(bet[l], sd_s[vl * 30 + c * 10 + l], s);
                vpf[vi * 3 + c] = Cs[(vl * 3 + c) * CS_STRIDE + tb] + s;
            }
        }
        u64 xs2[4], ys2[4], zs2[4];
#pragma unroll
        for (int vp = 0; vp < 4; vp++) {
            xs2[vp] = pk2(vpf[(2 * vp) * 3 + 0], vpf[(2 * vp + 1) * 3 + 0]);
            ys2[vp] = pk2(vpf[(2 * vp) * 3 + 1], vpf[(2 * vp + 1) * 3 + 1]);
            zs2[vp] = pk2(vpf[(2 * vp) * 3 + 2], vpf[(2 * vp + 1) * 3 + 2]);
        }
        u64 o2[4][3];
#pragma unroll
        for (int vp = 0; vp < 4; vp++) {
            o2[vp][0] = 0ULL; o2[vp][1] = 0ULL; o2[vp][2] = 0ULL;
        }

        for (int k = 0; k < KJ; k++) {
            float4 r0 = __ldg(Abase + k * 3 + 0);
            float4 r1 = __ldg(Abase + k * 3 + 1);
            float4 r2 = __ldg(Abase + k * 3 + 2);
            u64 r0x = pk2(r0.x, r0.x), r0y = pk2(r0.y, r0.y),
                r0z = pk2(r0.z, r0.z), r0w = pk2(r0.w, r0.w);
            u64 r1x = pk2(r1.x, r1.x), r1y = pk2(r1.y, r1.y),
                r1z = pk2(r1.z, r1.z), r1w = pk2(r1.w, r1.w);
            u64 r2x = pk2(r2.x, r2.x), r2y = pk2(r2.y, r2.y),
                r2z = pk2(r2.z, r2.z), r2w = pk2(r2.w, r2.w);
            const u64* wp = (const u64*)&w_s[k * 64 + tn * 16 + h2 * 8];
#pragma unroll
            for (int vp = 0; vp < 4; vp++) {
                u64 wv = wp[vp];
                u64 tx = ff2(r0x, xs2[vp], ff2(r0y, ys2[vp], ff2(r0z, zs2[vp], r0w)));
                u64 ty = ff2(r1x, xs2[vp], ff2(r1y, ys2[vp], ff2(r1z, zs2[vp], r1w)));
                u64 tz = ff2(r2x, xs2[vp], ff2(r2y, ys2[vp], ff2(r2z, zs2[vp], r2w)));
                o2[vp][0] = ff2(wv, tx, o2[vp][0]);
                o2[vp][1] = ff2(wv, ty, o2[vp][1]);
                o2[vp][2] = ff2(wv, tz, o2[vp][2]);
            }
        }

        // ---- store 24 coords for this half (float2: NC even -> always aligned)
        float ov[24];
#pragma unroll
        for (int vp = 0; vp < 4; vp++)
#pragma unroll
            for (int c = 0; c < 3; c++)
                upk2(o2[vp][c], ov[(2 * vp) * 3 + c], ov[(2 * vp + 1) * 3 + c]);
        int nbase = n0 + tn * 48 + h2 * 24;
        size_t base = (size_t)gb * NC + nbase;
        if (nbase + 24 <= NC) {
#pragma unroll
            for (int j = 0; j < 12; j++)
                *(float2*)&out[base + 2 * j] = make_float2(ov[2 * j], ov[2 * j + 1]);
        } else {
#pragma unroll
            for (int cj = 0; cj < 24; cj++)
                if (nbase + cj < NC) out[base + cj] = ov[cj];
        }
    }
}

// ============================================================================
extern "C" void kernel_launch(void* const* d_in, const int* in_sizes, int n_in,
                              void* d_out, int out_size)
{
    const float* body_pose     = (const float*)d_in[0];
    const float* betas         = (const float*)d_in[1];
    const float* global_orient = (const float*)d_in[2];
    const float* v_template    = (const float*)d_in[3];
    const float* shapedirs     = (const float*)d_in[4];
    const float* posedirs      = (const float*)d_in[5];
    const float* J_regressor   = (const float*)d_in[6];
    const float* lbs_weights   = (const float*)d_in[7];
    const int*   parents       = (const int*)d_in[8];
    float* out = (float*)d_out;

    static bool s_attr = false;
    if (!s_attr) {
        cudaFuncSetAttribute(k3_lbs, cudaFuncAttributeMaxDynamicSharedMemorySize,
                             SMEM_BYTES);
        s_attr = true;
    }

    k1a_jreduce<<<dim3(KJ, 8), 256>>>(J_regressor, v_template, shapedirs);
    k1b_combine<<<1, 256>>>();
    k2_batch<<<BATCH / 8, 256>>>(body_pose, betas, global_orient, parents, out);
    k3_lbs<<<dim3(16, 108), 256, SMEM_BYTES>>>(posedirs, lbs_weights, shapedirs,
                                               v_template, betas, out);
}

// round 6
// speedup vs baseline: 1.0933x; 1.0933x over previous
#include <cuda_runtime.h>
#include <cstdint>

#define BATCH 1024
#define NV 6890
#define KJ 24
#define NBETA 10
#define NPOSE 207
#define NPP 208          // 207 pose rows + 1 zero pad (=13*16)
#define NC 20670         // NV*3
#define NCHUNKS 13
#define NVSEG 864

// ---- scratch (device globals; no allocations allowed) ----
__device__ float g_JT0[KJ * 3];
__device__ float g_JS[KJ * 30];
__device__ float g_part[8 * KJ * 33];
__device__ float g_pfT[NPP * BATCH];          // pose feature^T [p][b], row 207 = 0
__device__ float g_A2f[KJ * 512 * 24];        // A batch-pair interleaved:
                                              // [k][b/2][e0..e11 as (b_even,b_odd) pairs]

// ---- output layout (concatenated tuple, float32) ----
#define OUT_JT   (BATCH * NV * 3)
#define OUT_J    (OUT_JT + BATCH * KJ * 3)
#define OUT_ROT  (OUT_J + BATCH * KJ * 3)

// ---- packed f32x2 helpers ----
typedef unsigned long long u64;
__device__ __forceinline__ u64 pk2(float lo, float hi) {
    u64 r; asm("mov.b64 %0, {%1, %2};" : "=l"(r) : "f"(lo), "f"(hi)); return r;
}
__device__ __forceinline__ void upk2(u64 v, float& lo, float& hi) {
    asm("mov.b64 {%0, %1}, %2;" : "=f"(lo), "=f"(hi) : "l"(v));
}
__device__ __forceinline__ u64 ff2(u64 a, u64 b, u64 c) {
    u64 d; asm("fma.rn.f32x2 %0, %1, %2, %3;" : "=l"(d) : "l"(a), "l"(b), "l"(c));
    return d;
}
__device__ __forceinline__ u64 add2(u64 a, u64 b) {
    u64 d; asm("add.rn.f32x2 %0, %1, %2;" : "=l"(d) : "l"(a), "l"(b));
    return d;
}

// ---- cp.async helpers ----
__device__ __forceinline__ void cpa16(uint32_t dst, const void* src, int sb) {
    asm volatile("cp.async.cg.shared.global [%0], [%1], 16, %2;"
                 :: "r"(dst), "l"(src), "r"(sb));
}
__device__ __forceinline__ void cpa8(uint32_t dst, const void* src, int sb) {
    asm volatile("cp.async.ca.shared.global [%0], [%1], 8, %2;"
                 :: "r"(dst), "l"(src), "r"(sb));
}
__device__ __forceinline__ void cpcommit() {
    asm volatile("cp.async.commit_group;");
}

#define MMA_TF32(d, a, b) \
    asm volatile("mma.sync.aligned.m16n8k8.row.col.f32.tf32.tf32.f32 " \
        "{%0,%1,%2,%3}, {%4,%5,%6,%7}, {%8,%9}, {%0,%1,%2,%3};" \
        : "+f"(d[0]), "+f"(d[1]), "+f"(d[2]), "+f"(d[3]) \
        : "r"(a[0]), "r"(a[1]), "r"(a[2]), "r"(a[3]), "r"(b[0]), "r"(b[1]))

// ============================================================================
// Kernel 1a/1b: JT0 = Jreg @ v_template; JS = Jreg . shapedirs (split over V)
// ============================================================================
__global__ void k1a_jreduce(const float* __restrict__ Jreg,
                            const float* __restrict__ vt,
                            const float* __restrict__ sd)
{
    int k = blockIdx.x;
    int seg = blockIdx.y;
    int tid = threadIdx.x;
    int v0 = seg * NVSEG;
    int v1 = min(NV, v0 + NVSEG);
    float acc[33];
#pragma unroll
    for (int e = 0; e < 33; e++) acc[e] = 0.f;

    for (int v = v0 + tid; v < v1; v += 256) {
        float j = Jreg[k * NV + v];
        const float* vp = vt + v * 3;
        acc[0] = fmaf(j, vp[0], acc[0]);
        acc[1] = fmaf(j, vp[1], acc[1]);
        acc[2] = fmaf(j, vp[2], acc[2]);
        const float* sp = sd + v * 30;
#pragma unroll
        for (int e = 0; e < 30; e++) acc[3 + e] = fmaf(j, sp[e], acc[3 + e]);
    }
#pragma unroll
    for (int e = 0; e < 33; e++) {
        for (int off = 16; off; off >>= 1)
            acc[e] += __shfl_down_sync(0xffffffffu, acc[e], off);
    }
    __shared__ float red[8][33];
    int lane = tid & 31, w = tid >> 5;
    if (lane == 0) {
#pragma unroll
        for (int e = 0; e < 33; e++) red[w][e] = acc[e];
    }
    __syncthreads();
    if (tid < 33) {
        float s = 0.f;
#pragma unroll
        for (int w2 = 0; w2 < 8; w2++) s += red[w2][tid];
        g_part[(k * 8 + seg) * 33 + tid] = s;
    }
}

__global__ void k1b_combine()
{
    int idx = threadIdx.x;
    for (; idx < KJ * 33; idx += 256) {
        int k = idx / 33, e = idx % 33;
        float s = 0.f;
#pragma unroll
        for (int seg = 0; seg < 8; seg++) s += g_part[(k * 8 + seg) * 33 + e];
        if (e < 3) g_JT0[k * 3 + e] = s;
        else       g_JS[k * 30 + (e - 3)] = s;
    }
}

// ============================================================================
// Kernel 2: 8 batches/block, one warp per batch. Rodrigues, pose feature,
// joints_t, kinematic chain, A matrices (batch-pair interleaved layout).
// ============================================================================
__global__ __launch_bounds__(256) void k2_batch(
    const float* __restrict__ body_pose,
    const float* __restrict__ betas,
    const float* __restrict__ global_orient,
    const int* __restrict__ parents,
    float* __restrict__ out)
{
    int w = threadIdx.x >> 5;
    int t = threadIdx.x & 31;
    int b = blockIdx.x * 8 + w;
    __shared__ float Rm[8][KJ][9];
    __shared__ float jt[8][KJ][3];
    __shared__ float rel[8][KJ][3];
    __shared__ float ch[8][KJ][12];

    if (t < KJ) {
        float ax, ay, az;
        if (t == 0) {
            ax = global_orient[b * 3 + 0];
            ay = global_orient[b * 3 + 1];
            az = global_orient[b * 3 + 2];
        } else {
            const float* p = body_pose + b * 69 + (t - 1) * 3;
            ax = p[0]; ay = p[1]; az = p[2];
        }
        float ex = ax + 1e-8f, ey = ay + 1e-8f, ez = az + 1e-8f;
        float angle = sqrtf(ex * ex + ey * ey + ez * ez);
        float inv = 1.0f / angle;
        float ux = ax * inv, uy = ay * inv, uz = az * inv;
        float s = sinf(angle), c = cosf(angle);
        float oc = 1.0f - c;
        float uu = ux * ux + uy * uy + uz * uz;
        float r0 = 1.0f + oc * (ux * ux - uu);
        float r1 = -s * uz + oc * (ux * uy);
        float r2 =  s * uy + oc * (ux * uz);
        float r3 =  s * uz + oc * (uy * ux);
        float r4 = 1.0f + oc * (uy * uy - uu);
        float r5 = -s * ux + oc * (uy * uz);
        float r6 = -s * uy + oc * (uz * ux);
        float r7 =  s * ux + oc * (uz * uy);
        float r8 = 1.0f + oc * (uz * uz - uu);
        Rm[w][t][0] = r0; Rm[w][t][1] = r1; Rm[w][t][2] = r2;
        Rm[w][t][3] = r3; Rm[w][t][4] = r4; Rm[w][t][5] = r5;
        Rm[w][t][6] = r6; Rm[w][t][7] = r7; Rm[w][t][8] = r8;

        float* ro = out + OUT_ROT + (size_t)b * 216 + t * 9;
        ro[0] = r0; ro[1] = r1; ro[2] = r2; ro[3] = r3; ro[4] = r4;
        ro[5] = r5; ro[6] = r6; ro[7] = r7; ro[8] = r8;

        if (t >= 1) {
            int p0 = (t - 1) * 9;
            g_pfT[(p0 + 0) * BATCH + b] = r0 - 1.0f;
            g_pfT[(p0 + 1) * BATCH + b] = r1;
            g_pfT[(p0 + 2) * BATCH + b] = r2;
            g_pfT[(p0 + 3) * BATCH + b] = r3;
            g_pfT[(p0 + 4) * BATCH + b] = r4 - 1.0f;
            g_pfT[(p0 + 5) * BATCH + b] = r5;
            g_pfT[(p0 + 6) * BATCH + b] = r6;
            g_pfT[(p0 + 7) * BATCH + b] = r7;
            g_pfT[(p0 + 8) * BATCH + b] = r8 - 1.0f;
        } else {
            g_pfT[207 * BATCH + b] = 0.0f;   // pad row
        }

#pragma unroll
        for (int cc = 0; cc < 3; cc++) {
            float s2 = g_JT0[t * 3 + cc];
#pragma unroll
            for (int l = 0; l < NBETA; l++)
                s2 = fmaf(g_JS[t * 30 + cc * 10 + l], betas[b * 10 + l], s2);
            jt[w][t][cc] = s2;
            out[OUT_JT + (size_t)b * 72 + t * 3 + cc] = s2;
        }
    }
    __syncwarp();
    if (t < KJ) {
        if (t == 0) {
            rel[w][0][0] = jt[w][0][0]; rel[w][0][1] = jt[w][0][1]; rel[w][0][2] = jt[w][0][2];
        } else {
            int p = parents[t];
            rel[w][t][0] = jt[w][t][0] - jt[w][p][0];
            rel[w][t][1] = jt[w][t][1] - jt[w][p][1];
            rel[w][t][2] = jt[w][t][2] - jt[w][p][2];
        }
    }
    __syncwarp();
    if (t < 12) {
        int i = t >> 2, j = t & 3;
        ch[w][0][t] = (j < 3) ? Rm[w][0][i * 3 + j] : rel[w][0][i];
    }
    __syncwarp();
    for (int k = 1; k < KJ; k++) {
        int p = parents[k];
        if (t < 12) {
            int i = t >> 2, j = t & 3;
            float v;
            if (j < 3) {
                v = ch[w][p][i * 4 + 0] * Rm[w][k][0 * 3 + j]
                  + ch[w][p][i * 4 + 1] * Rm[w][k][1 * 3 + j]
                  + ch[w][p][i * 4 + 2] * Rm[w][k][2 * 3 + j];
            } else {
                v = ch[w][p][i * 4 + 0] * rel[w][k][0]
                  + ch[w][p][i * 4 + 1] * rel[w][k][1]
                  + ch[w][p][i * 4 + 2] * rel[w][k][2]
                  + ch[w][p][i * 4 + 3];
            }
            ch[w][k][t] = v;
        }
        __syncwarp();
    }
    if (t < KJ) {
        out[OUT_J + (size_t)b * 72 + t * 3 + 0] = ch[w][t][3];
        out[OUT_J + (size_t)b * 72 + t * 3 + 1] = ch[w][t][7];
        out[OUT_J + (size_t)b * 72 + t * 3 + 2] = ch[w][t][11];
        // A = [R | t - R*joints_t], stored batch-pair interleaved
        int bp = b >> 1, sel = b & 1;
        size_t abase = ((size_t)t * 512 + bp) * 24 + sel;
#pragma unroll
        for (int i = 0; i < 3; i++) {
            float tr = ch[w][t][i * 4 + 3]
                     - (ch[w][t][i * 4 + 0] * jt[w][t][0]
                      + ch[w][t][i * 4 + 1] * jt[w][t][1]
                      + ch[w][t][i * 4 + 2] * jt[w][t][2]);
            g_A2f[abase + (i * 4 + 0) * 2] = ch[w][t][i * 4 + 0];
            g_A2f[abase + (i * 4 + 1) * 2] = ch[w][t][i * 4 + 1];
            g_A2f[abase + (i * 4 + 2) * 2] = ch[w][t][i * 4 + 2];
            g_A2f[abase + (i * 4 + 3) * 2] = tr;
        }
    }
}

// ============================================================================
// Kernel 3: tf32 mma.sync GEMM + fp32 shape + FFMA2 LBS (batch-pair packed).
// ONE CTA of 512 threads (16 warps -> 4/SMSP). Block tile 192 coords x 64 b.
// Warp tile 48x16 (3x2 frags). 4-stage cp.async ring, one barrier per chunk.
// Epilogue: 16-coord groups x 32 batch-pairs; A/w/vp all loaded pre-packed.
// ============================================================================
#define SF_STAGE 4352                 // A 16x200=3200 + B 16x72=1152
#define CS_STRIDE 66                  // Csm 192x66 = 12672 (aliases stages)
#define S_W2    17408                 // [24][64] u64 = 3072 floats
#define S_A2    (S_W2 + 3072)         // [24][32][12] u64 = 18432 floats
#define S_SD    (S_A2 + 18432)        // 64*30 = 1920
#define S_VT    (S_SD + 1920)         // 192
#define S_BET   (S_VT + 192)          // 640
#define SMEM_FL (S_BET + 640)         // 41664 floats
#define SMEM_BYTES (SMEM_FL * 4)      // 166656

__device__ __forceinline__ void k3_load_stage(uint32_t smb,
                                              const float* __restrict__ posedirs,
                                              int n0, int kc, int st, int tid)
{
    if (tid < 256) {
#pragma unroll
        for (int j = 0; j < 6; j++) {
            int i = tid + j * 256;            // < 1536
            int row = i / 96, c2 = i % 96;
            int p = kc * 16 + row;
            int col = n0 + c2 * 2;
            int sb = 0;
            if (p < NPOSE) {
                int rem = NC - col;
                sb = (rem >= 2) ? 8 : 0;
            }
            const float* src = posedirs + (size_t)min(p, NPOSE - 1) * NC
                                        + (sb ? col : 0);
            cpa8(smb + (uint32_t)(st * SF_STAGE + row * 200 + c2 * 2) * 4, src, sb);
        }
        {
            int row = tid / 16, c4 = tid % 16;
            int p = kc * 16 + row;
            int bBase = blockIdx.x * 64;
            cpa16(smb + (uint32_t)(st * SF_STAGE + 3200 + row * 72 + c4 * 4) * 4,
                  g_pfT + (size_t)p * BATCH + bBase + c4 * 4, 16);
        }
    }
}

__global__ __launch_bounds__(512, 1) void k3_lbs(
    const float* __restrict__ posedirs,
    const float* __restrict__ lbs_w,
    const float* __restrict__ shapedirs,
    const float* __restrict__ v_template,
    const float* __restrict__ betas,
    float* __restrict__ out)
{
    extern __shared__ float sm[];
    uint32_t smb = (uint32_t)__cvta_generic_to_shared(sm);
    int tid = threadIdx.x;
    int lane = tid & 31, warp = tid >> 5;
    int bBase = blockIdx.x * 64;
    int n0 = blockIdx.y * 192;
    int v0 = n0 / 3;
    int mW = (warp & 3) * 48;
    int nW = (warp >> 2) * 16;

    // ---- epilogue tables via cp.async (group 0) ----
    {
        int validf = (NV - v0) * 30; if (validf > 1920) validf = 1920;
        if (tid < 480) {
            int fo = tid * 4;
            int rem = validf - fo;
            int sb = rem >= 4 ? 16 : (rem > 0 ? rem * 4 : 0);
            cpa16(smb + (uint32_t)(S_SD + fo) * 4,
                  shapedirs + (size_t)v0 * 30 + (sb ? fo : 0), sb);
        }
        if (tid < 48) {
            int fo = tid * 4;
            int validv = (NV - v0) * 3; if (validv > 192) validv = 192;
            int rem = validv - fo;
            int sb = rem >= 4 ? 16 : (rem > 0 ? rem * 4 : 0);
            cpa16(smb + (uint32_t)(S_VT + fo) * 4,
                  v_template + (size_t)v0 * 3 + (sb ? fo : 0), sb);
        }
        if (tid < 160) {
            cpa16(smb + (uint32_t)(S_BET + tid * 4) * 4,
                  betas + (size_t)bBase * 10 + tid * 4, 16);
        }
        // A2 table: [24][32][12] u64 = 18432 floats = 4608 x 16B
#pragma unroll
        for (int j = 0; j < 9; j++) {
            int i = tid + j * 512;            // < 4608
            int k = i / 192;
            int rem4 = (i % 192) * 4;
            cpa16(smb + (uint32_t)(S_A2 + k * 768 + rem4) * 4,
                  g_A2f + ((size_t)k * 512 + (bBase >> 1)) * 24 + rem4, 16);
        }
    }
    cpcommit();

    // ---- prefetch GEMM chunks 0, 1 ----
    k3_load_stage(smb, posedirs, n0, 0, 0, tid); cpcommit();
    k3_load_stage(smb, posedirs, n0, 1, 1, tid); cpcommit();

    // ---- w2 table: duplicated (w,w) pairs, [24][64] u64 ----
#pragma unroll
    for (int j = 0; j < 3; j++) {
        int i = tid + j * 512;                // < 1536
        int k = i >> 6, vl = i & 63;
        int vg = v0 + vl;
        float wv = (vg < NV) ? lbs_w[vg * KJ + k] : 0.f;
        *(float2*)&sm[S_W2 + i * 2] = make_float2(wv, wv);
    }

    float acc[3][2][4];
#pragma unroll
    for (int it = 0; it < 3; it++)
#pragma unroll
        for (int jt = 0; jt < 2; jt++)
#pragma unroll
            for (int e = 0; e < 4; e++) acc[it][jt][e] = 0.f;

    // ---- main k-loop: one barrier per chunk ----
    for (int kc = 0; kc < NCHUNKS; kc++) {
        if (kc + 2 < NCHUNKS)
            k3_load_stage(smb, posedirs, n0, kc + 2, (kc + 2) & 3, tid);
        cpcommit();
        asm volatile("cp.async.wait_group 2;");
        __syncthreads();

        const float* As = sm + (kc & 3) * SF_STAGE;
        const float* Bs = As + 3200;
#pragma unroll
        for (int kk = 0; kk < 2; kk++) {
            int k0 = kk * 8;
            uint32_t a[3][4], b[2][2];
            int ar0 = (k0 + (lane & 3)) * 200 + mW + (lane >> 2);
            int ar1 = ar0 + 4 * 200;
#pragma unroll
            for (int it = 0; it < 3; it++) {
                a[it][0] = __float_as_uint(As[ar0 + it * 16]);
                a[it][1] = __float_as_uint(As[ar0 + it * 16 + 8]);
                a[it][2] = __float_as_uint(As[ar1 + it * 16]);
                a[it][3] = __float_as_uint(As[ar1 + it * 16 + 8]);
            }
            int br0 = (k0 + (lane & 3)) * 72 + nW + (lane >> 2);
            int br1 = br0 + 4 * 72;
#pragma unroll
            for (int jt = 0; jt < 2; jt++) {
                b[jt][0] = __float_as_uint(Bs[br0 + jt * 8]);
                b[jt][1] = __float_as_uint(Bs[br1 + jt * 8]);
            }
#pragma unroll
            for (int it = 0; it < 3; it++)
#pragma unroll
                for (int jt = 0; jt < 2; jt++)
                    MMA_TF32(acc[it][jt], a[it], b[jt]);
        }
    }
    __syncthreads();   // all stage reads done before Csm overwrites stages

    // ---- dump accumulators to Csm (stage region is dead) ----
    {
        float* Cs = sm;
#pragma unroll
        for (int it = 0; it < 3; it++)
#pragma unroll
            for (int jt = 0; jt < 2; jt++) {
                int m = mW + it * 16 + (lane >> 2);
                int n = nW + jt * 8 + 2 * (lane & 3);
                Cs[m * CS_STRIDE + n]           = acc[it][jt][0];
                Cs[m * CS_STRIDE + n + 1]       = acc[it][jt][1];
                Cs[(m + 8) * CS_STRIDE + n]     = acc[it][jt][2];
                Cs[(m + 8) * CS_STRIDE + n + 1] = acc[it][jt][3];
            }
    }
    asm volatile("cp.async.wait_group 0;");
    __syncthreads();

    // ---- epilogue: 16 coord-groups (12 coords) x 32 batch-pairs ----
    int tn  = tid & 15;      // coord group: coords tn*12..+11 (vertices tn*4..+3)
    int tbp = tid >> 4;      // batch pair: b0 = bBase+2*tbp, b1 = b0+1
    const float* Cs   = sm;
    const float* sd_s = sm + S_SD;
    const float* vt_s = sm + S_VT;
    const float* bt_s = sm + S_BET;
    const u64*   A2p  = (const u64*)&sm[S_A2];
    const u64*   w2p  = (const u64*)&sm[S_W2];

    // betas for both batches
    float bet0[10], bet1[10];
#pragma unroll
    for (int l = 0; l < NBETA; l++) {
        bet0[l] = bt_s[(2 * tbp) * 10 + l];
        bet1[l] = bt_s[(2 * tbp + 1) * 10 + l];
    }

    // v_posed, packed (b0,b1) per coord
    u64 xs2[4], ys2[4], zs2[4];
#pragma unroll
    for (int vi = 0; vi < 4; vi++) {
        int vl = tn * 4 + vi;
#pragma unroll
        for (int c = 0; c < 3; c++) {
            float vtc = vt_s[vl * 3 + c];
            float sdv[10];
#pragma unroll
            for (int l = 0; l < NBETA; l++) sdv[l] = sd_s[vl * 30 + c * 10 + l];
            float s0 = vtc, s1 = vtc;
#pragma unroll
            for (int l = 0; l < NBETA; l++) {
                s0 = fmaf(bet0[l], sdv[l], s0);
                s1 = fmaf(bet1[l], sdv[l], s1);
            }
            u64 cs2 = *(const u64*)&Cs[(vl * 3 + c) * CS_STRIDE + 2 * tbp];
            u64 vp2 = add2(cs2, pk2(s0, s1));
            if (c == 0) xs2[vi] = vp2;
            else if (c == 1) ys2[vi] = vp2;
            else zs2[vi] = vp2;
        }
    }

    u64 o2[4][3];
#pragma unroll
    for (int vi = 0; vi < 4; vi++) {
        o2[vi][0] = 0ULL; o2[vi][1] = 0ULL; o2[vi][2] = 0ULL;
    }

    // LBS: A rows already packed as (b0,b1) u64 -> zero broadcasts
    for (int k = 0; k < KJ; k++) {
        const u64* Ar = A2p + ((size_t)k * 32 + tbp) * 12;
        u64 r0x = Ar[0], r0y = Ar[1], r0z = Ar[2], r0w = Ar[3];
        u64 r1x = Ar[4], r1y = Ar[5], r1z = Ar[6], r1w = Ar[7];
        u64 r2x = Ar[8], r2y = Ar[9], r2z = Ar[10], r2w = Ar[11];
        const u64* wr = w2p + k * 64 + tn * 4;
#pragma unroll
        for (int vi = 0; vi < 4; vi++) {
            u64 wv = wr[vi];
            u64 tx = ff2(r0x, xs2[vi], ff2(r0y, ys2[vi], ff2(r0z, zs2[vi], r0w)));
            u64 ty = ff2(r1x, xs2[vi], ff2(r1y, ys2[vi], ff2(r1z, zs2[vi], r1w)));
            u64 tz = ff2(r2x, xs2[vi], ff2(r2y, ys2[vi], ff2(r2z, zs2[vi], r2w)));
            o2[vi][0] = ff2(wv, tx, o2[vi][0]);
            o2[vi][1] = ff2(wv, ty, o2[vi][1]);
            o2[vi][2] = ff2(wv, tz, o2[vi][2]);
        }
    }

    // ---- unpack to per-batch coord runs and store (float2, NC even) ----
    float ov0[12], ov1[12];
#pragma unroll
    for (int vi = 0; vi < 4; vi++)
#pragma unroll
        for (int c = 0; c < 3; c++)
            upk2(o2[vi][c], ov0[vi * 3 + c], ov1[vi * 3 + c]);

    int nbase = n0 + tn * 12;
    size_t base0 = (size_t)(bBase + 2 * tbp) * NC + nbase;
    size_t base1 = base0 + NC;
    if (nbase + 12 <= NC) {
#pragma unroll
        for (int j = 0; j < 6; j++) {
            *(float2*)&out[base0 + 2 * j] = make_float2(ov0[2 * j], ov0[2 * j + 1]);
            *(float2*)&out[base1 + 2 * j] = make_float2(ov1[2 * j], ov1[2 * j + 1]);
        }
    } else {
#pragma unroll
        for (int cj = 0; cj < 12; cj++) {
            if (nbase + cj < NC) {
                out[base0 + cj] = ov0[cj];
                out[base1 + cj] = ov1[cj];
            }
        }
    }
}

// ============================================================================
extern "C" void kernel_launch(void* const* d_in, const int* in_sizes, int n_in,
                              void* d_out, int out_size)
{
    const float* body_pose     = (const float*)d_in[0];
    const float* betas         = (const float*)d_in[1];
    const float* global_orient = (const float*)d_in[2];
    const float* v_template    = (const float*)d_in[3];
    const float* shapedirs     = (const float*)d_in[4];
    const float* posedirs      = (const float*)d_in[5];
    const float* J_regressor   = (const float*)d_in[6];
    const float* lbs_weights   = (const float*)d_in[7];
    const int*   parents       = (const int*)d_in[8];
    float* out = (float*)d_out;

    static bool s_attr = false;
    if (!s_attr) {
        cudaFuncSetAttribute(k3_lbs, cudaFuncAttributeMaxDynamicSharedMemorySize,
                             SMEM_BYTES);
        s_attr = true;
    }

    k1a_jreduce<<<dim3(KJ, 8), 256>>>(J_regressor, v_template, shapedirs);
    k1b_combine<<<1, 256>>>();
    k2_batch<<<BATCH / 8, 256>>>(body_pose, betas, global_orient, parents, out);
    k3_lbs<<<dim3(16, 108), 512, SMEM_BYTES>>>(posedirs, lbs_weights, shapedirs,
                                               v_template, betas, out);
}

// round 7
// speedup vs baseline: 1.1109x; 1.0161x over previous
#include <cuda_runtime.h>
#include <cstdint>

#define BATCH 1024
#define NV 6890
#define KJ 24
#define NBETA 10
#define NPOSE 207
#define NPP 208          // 207 pose rows + 1 zero pad (=13*16)
#define NC 20670         // NV*3
#define NCHUNKS 13
#define NVSEG 864

// ---- scratch (device globals; no allocations allowed) ----
__device__ float g_JT0[KJ * 3];
__device__ float g_JS[KJ * 30];
__device__ float g_part[8 * KJ * 33];
__device__ float g_pfT[NPP * BATCH];          // pose feature^T [p][b], row 207 = 0
__device__ float g_A2f[KJ * 512 * 24];        // A batch-pair interleaved:
                                              // [k][b/2][e0..e11 as (b_even,b_odd) pairs]

// ---- output layout (concatenated tuple, float32) ----
#define OUT_JT   (BATCH * NV * 3)
#define OUT_J    (OUT_JT + BATCH * KJ * 3)
#define OUT_ROT  (OUT_J + BATCH * KJ * 3)

// ---- packed f32x2 helpers ----
typedef unsigned long long u64;
__device__ __forceinline__ u64 pk2(float lo, float hi) {
    u64 r; asm("mov.b64 %0, {%1, %2};" : "=l"(r) : "f"(lo), "f"(hi)); return r;
}
__device__ __forceinline__ void upk2(u64 v, float& lo, float& hi) {
    asm("mov.b64 {%0, %1}, %2;" : "=f"(lo), "=f"(hi) : "l"(v));
}
__device__ __forceinline__ u64 ff2(u64 a, u64 b, u64 c) {
    u64 d; asm("fma.rn.f32x2 %0, %1, %2, %3;" : "=l"(d) : "l"(a), "l"(b), "l"(c));
    return d;
}
__device__ __forceinline__ u64 add2(u64 a, u64 b) {
    u64 d; asm("add.rn.f32x2 %0, %1, %2;" : "=l"(d) : "l"(a), "l"(b));
    return d;
}

// ---- cp.async helpers ----
__device__ __forceinline__ void cpa16(uint32_t dst, const void* src, int sb) {
    asm volatile("cp.async.cg.shared.global [%0], [%1], 16, %2;"
                 :: "r"(dst), "l"(src), "r"(sb));
}
__device__ __forceinline__ void cpa8(uint32_t dst, const void* src, int sb) {
    asm volatile("cp.async.ca.shared.global [%0], [%1], 8, %2;"
                 :: "r"(dst), "l"(src), "r"(sb));
}
__device__ __forceinline__ void cpcommit() {
    asm volatile("cp.async.commit_group;");
}

#define MMA_TF32(d, a, b) \
    asm volatile("mma.sync.aligned.m16n8k8.row.col.f32.tf32.tf32.f32 " \
        "{%0,%1,%2,%3}, {%4,%5,%6,%7}, {%8,%9}, {%0,%1,%2,%3};" \
        : "+f"(d[0]), "+f"(d[1]), "+f"(d[2]), "+f"(d[3]) \
        : "r"(a[0]), "r"(a[1]), "r"(a[2]), "r"(a[3]), "r"(b[0]), "r"(b[1]))

// ============================================================================
// Kernel 1a/1b: JT0 = Jreg @ v_template; JS = Jreg . shapedirs (split over V)
// ============================================================================
__global__ void k1a_jreduce(const float* __restrict__ Jreg,
                            const float* __restrict__ vt,
                            const float* __restrict__ sd)
{
    int k = blockIdx.x;
    int seg = blockIdx.y;
    int tid = threadIdx.x;
    int v0 = seg * NVSEG;
    int v1 = min(NV, v0 + NVSEG);
    float acc[33];
#pragma unroll
    for (int e = 0; e < 33; e++) acc[e] = 0.f;

    for (int v = v0 + tid; v < v1; v += 256) {
        float j = Jreg[k * NV + v];
        const float* vp = vt + v * 3;
        acc[0] = fmaf(j, vp[0], acc[0]);
        acc[1] = fmaf(j, vp[1], acc[1]);
        acc[2] = fmaf(j, vp[2], acc[2]);
        const float* sp = sd + v * 30;
#pragma unroll
        for (int e = 0; e < 30; e++) acc[3 + e] = fmaf(j, sp[e], acc[3 + e]);
    }
#pragma unroll
    for (int e = 0; e < 33; e++) {
        for (int off = 16; off; off >>= 1)
            acc[e] += __shfl_down_sync(0xffffffffu, acc[e], off);
    }
    __shared__ float red[8][33];
    int lane = tid & 31, w = tid >> 5;
    if (lane == 0) {
#pragma unroll
        for (int e = 0; e < 33; e++) red[w][e] = acc[e];
    }
    __syncthreads();
    if (tid < 33) {
        float s = 0.f;
#pragma unroll
        for (int w2 = 0; w2 < 8; w2++) s += red[w2][tid];
        g_part[(k * 8 + seg) * 33 + tid] = s;
    }
}

__global__ void k1b_combine()
{
    int idx = threadIdx.x;
    for (; idx < KJ * 33; idx += 256) {
        int k = idx / 33, e = idx % 33;
        float s = 0.f;
#pragma unroll
        for (int seg = 0; seg < 8; seg++) s += g_part[(k * 8 + seg) * 33 + e];
        if (e < 3) g_JT0[k * 3 + e] = s;
        else       g_JS[k * 30 + (e - 3)] = s;
    }
}

// ============================================================================
// Kernel 2: 8 batches/block, one warp per batch. Rodrigues, pose feature,
// joints_t, kinematic chain, A matrices (batch-pair interleaved layout).
// ============================================================================
__global__ __launch_bounds__(256) void k2_batch(
    const float* __restrict__ body_pose,
    const float* __restrict__ betas,
    const float* __restrict__ global_orient,
    const int* __restrict__ parents,
    float* __restrict__ out)
{
    int w = threadIdx.x >> 5;
    int t = threadIdx.x & 31;
    int b = blockIdx.x * 8 + w;
    __shared__ float Rm[8][KJ][9];
    __shared__ float jt[8][KJ][3];
    __shared__ float rel[8][KJ][3];
    __shared__ float ch[8][KJ][12];

    if (t < KJ) {
        float ax, ay, az;
        if (t == 0) {
            ax = global_orient[b * 3 + 0];
            ay = global_orient[b * 3 + 1];
            az = global_orient[b * 3 + 2];
        } else {
            const float* p = body_pose + b * 69 + (t - 1) * 3;
            ax = p[0]; ay = p[1]; az = p[2];
        }
        float ex = ax + 1e-8f, ey = ay + 1e-8f, ez = az + 1e-8f;
        float angle = sqrtf(ex * ex + ey * ey + ez * ez);
        float inv = 1.0f / angle;
        float ux = ax * inv, uy = ay * inv, uz = az * inv;
        float s = sinf(angle), c = cosf(angle);
        float oc = 1.0f - c;
        float uu = ux * ux + uy * uy + uz * uz;
        float r0 = 1.0f + oc * (ux * ux - uu);
        float r1 = -s * uz + oc * (ux * uy);
        float r2 =  s * uy + oc * (ux * uz);
        float r3 =  s * uz + oc * (uy * ux);
        float r4 = 1.0f + oc * (uy * uy - uu);
        float r5 = -s * ux + oc * (uy * uz);
        float r6 = -s * uy + oc * (uz * ux);
        float r7 =  s * ux + oc * (uz * uy);
        float r8 = 1.0f + oc * (uz * uz - uu);
        Rm[w][t][0] = r0; Rm[w][t][1] = r1; Rm[w][t][2] = r2;
        Rm[w][t][3] = r3; Rm[w][t][4] = r4; Rm[w][t][5] = r5;
        Rm[w][t][6] = r6; Rm[w][t][7] = r7; Rm[w][t][8] = r8;

        float* ro = out + OUT_ROT + (size_t)b * 216 + t * 9;
        ro[0] = r0; ro[1] = r1; ro[2] = r2; ro[3] = r3; ro[4] = r4;
        ro[5] = r5; ro[6] = r6; ro[7] = r7; ro[8] = r8;

        if (t >= 1) {
            int p0 = (t - 1) * 9;
            g_pfT[(p0 + 0) * BATCH + b] = r0 - 1.0f;
            g_pfT[(p0 + 1) * BATCH + b] = r1;
            g_pfT[(p0 + 2) * BATCH + b] = r2;
            g_pfT[(p0 + 3) * BATCH + b] = r3;
            g_pfT[(p0 + 4) * BATCH + b] = r4 - 1.0f;
            g_pfT[(p0 + 5) * BATCH + b] = r5;
            g_pfT[(p0 + 6) * BATCH + b] = r6;
            g_pfT[(p0 + 7) * BATCH + b] = r7;
            g_pfT[(p0 + 8) * BATCH + b] = r8 - 1.0f;
        } else {
            g_pfT[207 * BATCH + b] = 0.0f;   // pad row
        }

#pragma unroll
        for (int cc = 0; cc < 3; cc++) {
            float s2 = g_JT0[t * 3 + cc];
#pragma unroll
            for (int l = 0; l < NBETA; l++)
                s2 = fmaf(g_JS[t * 30 + cc * 10 + l], betas[b * 10 + l], s2);
            jt[w][t][cc] = s2;
            out[OUT_JT + (size_t)b * 72 + t * 3 + cc] = s2;
        }
    }
    __syncwarp();
    if (t < KJ) {
        if (t == 0) {
            rel[w][0][0] = jt[w][0][0]; rel[w][0][1] = jt[w][0][1]; rel[w][0][2] = jt[w][0][2];
        } else {
            int p = parents[t];
            rel[w][t][0] = jt[w][t][0] - jt[w][p][0];
            rel[w][t][1] = jt[w][t][1] - jt[w][p][1];
            rel[w][t][2] = jt[w][t][2] - jt[w][p][2];
        }
    }
    __syncwarp();
    if (t < 12) {
        int i = t >> 2, j = t & 3;
        ch[w][0][t] = (j < 3) ? Rm[w][0][i * 3 + j] : rel[w][0][i];
    }
    __syncwarp();
    for (int k = 1; k < KJ; k++) {
        int p = parents[k];
        if (t < 12) {
            int i = t >> 2, j = t & 3;
            float v;
            if (j < 3) {
                v = ch[w][p][i * 4 + 0] * Rm[w][k][0 * 3 + j]
                  + ch[w][p][i * 4 + 1] * Rm[w][k][1 * 3 + j]
                  + ch[w][p][i * 4 + 2] * Rm[w][k][2 * 3 + j];
            } else {
                v = ch[w][p][i * 4 + 0] * rel[w][k][0]
                  + ch[w][p][i * 4 + 1] * rel[w][k][1]
                  + ch[w][p][i * 4 + 2] * rel[w][k][2]
                  + ch[w][p][i * 4 + 3];
            }
            ch[w][k][t] = v;
        }
        __syncwarp();
    }
    if (t < KJ) {
        out[OUT_J + (size_t)b * 72 + t * 3 + 0] = ch[w][t][3];
        out[OUT_J + (size_t)b * 72 + t * 3 + 1] = ch[w][t][7];
        out[OUT_J + (size_t)b * 72 + t * 3 + 2] = ch[w][t][11];
        // A = [R | t - R*joints_t], stored batch-pair interleaved
        int bp = b >> 1, sel = b & 1;
        size_t abase = ((size_t)t * 512 + bp) * 24 + sel;
#pragma unroll
        for (int i = 0; i < 3; i++) {
            float tr = ch[w][t][i * 4 + 3]
                     - (ch[w][t][i * 4 + 0] * jt[w][t][0]
                      + ch[w][t][i * 4 + 1] * jt[w][t][1]
                      + ch[w][t][i * 4 + 2] * jt[w][t][2]);
            g_A2f[abase + (i * 4 + 0) * 2] = ch[w][t][i * 4 + 0];
            g_A2f[abase + (i * 4 + 1) * 2] = ch[w][t][i * 4 + 1];
            g_A2f[abase + (i * 4 + 2) * 2] = tr * 0.0f + ch[w][t][i * 4 + 2];
            g_A2f[abase + (i * 4 + 3) * 2] = tr;
        }
    }
}

// ============================================================================
// Kernel 3: warp-specialized.
// Warps 0-7: tf32 mma GEMM, 192x64 block tile, 48x32 warp tile (4m x 2n),
//            4-stage cp.async ring, named barrier (bar.sync 1,256).
// Warps 8-15: stage epilogue tables (cp.async), build w2, precompute shape
//             blend table vpsh (batch-pair packed).
// Then one __syncthreads and all 16 warps run the packed FFMA2 LBS epilogue.
// ============================================================================
#define SF_STAGE 4352                 // A 16x200=3200 + B 16x72=1152
#define CS_STRIDE 66                  // Csm 192x66 = 12672 (aliases stages)
#define S_W2    17408                 // [24][64] u64 = 3072 floats
#define S_A2    (S_W2 + 3072)         // [24][32][12] u64 = 18432 floats
#define S_SD    (S_A2 + 18432)        // 64*30 = 1920
#define S_VT    (S_SD + 1920)         // 192
#define S_BET   (S_VT + 192)          // 640
#define S_VP    (S_BET + 640)         // [192 coords][33 u64 pad] = 12672 floats
#define SMEM_FL (S_VP + 12672)        // 54336 floats
#define SMEM_BYTES (SMEM_FL * 4)      // 217344

__device__ __forceinline__ void k3_load_stage(uint32_t smb,
                                              const float* __restrict__ posedirs,
                                              int n0, int kc, int st, int tid)
{
#pragma unroll
    for (int j = 0; j < 6; j++) {
        int i = tid + j * 256;            // < 1536
        int row = i / 96, c2 = i % 96;
        int p = kc * 16 + row;
        int col = n0 + c2 * 2;
        int sb = 0;
        if (p < NPOSE) {
            int rem = NC - col;
            sb = (rem >= 2) ? 8 : 0;
        }
        const float* src = posedirs + (size_t)min(p, NPOSE - 1) * NC
                                    + (sb ? col : 0);
        cpa8(smb + (uint32_t)(st * SF_STAGE + row * 200 + c2 * 2) * 4, src, sb);
    }
    {
        int row = tid / 16, c4 = tid % 16;
        int p = kc * 16 + row;
        int bBase = blockIdx.x * 64;
        cpa16(smb + (uint32_t)(st * SF_STAGE + 3200 + row * 72 + c4 * 4) * 4,
              g_pfT + (size_t)p * BATCH + bBase + c4 * 4, 16);
    }
}

__global__ __launch_bounds__(512, 1) void k3_lbs(
    const float* __restrict__ posedirs,
    const float* __restrict__ lbs_w,
    const float* __restrict__ shapedirs,
    const float* __restrict__ v_template,
    const float* __restrict__ betas,
    float* __restrict__ out)
{
    extern __shared__ float sm[];
    uint32_t smb = (uint32_t)__cvta_generic_to_shared(sm);
    int tid = threadIdx.x;
    int lane = tid & 31, warp = tid >> 5;
    int bBase = blockIdx.x * 64;
    int n0 = blockIdx.y * 192;
    int v0 = n0 / 3;

    if (tid < 256) {
        // ==================== GEMM warps ====================
        int mW = (warp & 3) * 48;
        int nW = (warp >> 2) * 32;

        k3_load_stage(smb, posedirs, n0, 0, 0, tid); cpcommit();
        k3_load_stage(smb, posedirs, n0, 1, 1, tid); cpcommit();

        float acc[3][4][4];
#pragma unroll
        for (int it = 0; it < 3; it++)
#pragma unroll
            for (int jt = 0; jt < 4; jt++)
#pragma unroll
                for (int e = 0; e < 4; e++) acc[it][jt][e] = 0.f;

        for (int kc = 0; kc < NCHUNKS; kc++) {
            if (kc + 2 < NCHUNKS)
                k3_load_stage(smb, posedirs, n0, kc + 2, (kc + 2) & 3, tid);
            cpcommit();
            asm volatile("cp.async.wait_group 2;");
            asm volatile("bar.sync 1, 256;");

            const float* As = sm + (kc & 3) * SF_STAGE;
            const float* Bs = As + 3200;
#pragma unroll
            for (int kk = 0; kk < 2; kk++) {
                int k0 = kk * 8;
                uint32_t a[3][4], b[4][2];
                int ar0 = (k0 + (lane & 3)) * 200 + mW + (lane >> 2);
                int ar1 = ar0 + 4 * 200;
#pragma unroll
                for (int it = 0; it < 3; it++) {
                    a[it][0] = __float_as_uint(As[ar0 + it * 16]);
                    a[it][1] = __float_as_uint(As[ar0 + it * 16 + 8]);
                    a[it][2] = __float_as_uint(As[ar1 + it * 16]);
                    a[it][3] = __float_as_uint(As[ar1 + it * 16 + 8]);
                }
                int br0 = (k0 + (lane & 3)) * 72 + nW + (lane >> 2);
                int br1 = br0 + 4 * 72;
#pragma unroll
                for (int jt = 0; jt < 4; jt++) {
                    b[jt][0] = __float_as_uint(Bs[br0 + jt * 8]);
                    b[jt][1] = __float_as_uint(Bs[br1 + jt * 8]);
                }
#pragma unroll
                for (int it = 0; it < 3; it++)
#pragma unroll
                    for (int jt = 0; jt < 4; jt++)
                        MMA_TF32(acc[it][jt], a[it], b[jt]);
            }
        }
        asm volatile("bar.sync 1, 256;");   // all GEMM reads done

        // dump accumulators to Csm (stage region is dead for GEMM warps)
        float* Cs = sm;
#pragma unroll
        for (int it = 0; it < 3; it++)
#pragma unroll
            for (int jt = 0; jt < 4; jt++) {
                int m = mW + it * 16 + (lane >> 2);
                int n = nW + jt * 8 + 2 * (lane & 3);
                Cs[m * CS_STRIDE + n]           = acc[it][jt][0];
                Cs[m * CS_STRIDE + n + 1]       = acc[it][jt][1];
                Cs[(m + 8) * CS_STRIDE + n]     = acc[it][jt][2];
                Cs[(m + 8) * CS_STRIDE + n + 1] = acc[it][jt][3];
            }
    } else {
        // ==================== helper warps ====================
        int h = tid - 256;

        // epilogue tables (our own commit group)
        {
            int validf = (NV - v0) * 30; if (validf > 1920) validf = 1920;
#pragma unroll
            for (int j = 0; j < 2; j++) {
                int i = h + j * 256;
                if (i < 480) {
                    int fo = i * 4;
                    int rem = validf - fo;
                    int sb = rem >= 4 ? 16 : (rem > 0 ? rem * 4 : 0);
                    cpa16(smb + (uint32_t)(S_SD + fo) * 4,
                          shapedirs + (size_t)v0 * 30 + (sb ? fo : 0), sb);
                }
            }
            if (h < 48) {
                int fo = h * 4;
                int validv = (NV - v0) * 3; if (validv > 192) validv = 192;
                int rem = validv - fo;
                int sb = rem >= 4 ? 16 : (rem > 0 ? rem * 4 : 0);
                cpa16(smb + (uint32_t)(S_VT + fo) * 4,
                      v_template + (size_t)v0 * 3 + (sb ? fo : 0), sb);
            }
            if (h < 160) {
                cpa16(smb + (uint32_t)(S_BET + h * 4) * 4,
                      betas + (size_t)bBase * 10 + h * 4, 16);
            }
            // A2 table: [24][32][12] u64 = 4608 x 16B
#pragma unroll
            for (int j = 0; j < 18; j++) {
                int i = h + j * 256;            // < 4608
                int k = i / 192;
                int rem4 = (i % 192) * 4;
                cpa16(smb + (uint32_t)(S_A2 + k * 768 + rem4) * 4,
                      g_A2f + ((size_t)k * 512 + (bBase >> 1)) * 24 + rem4, 16);
            }
        }
        cpcommit();

        // w2 table: duplicated (w,w) pairs, [24][64] u64 (plain LDG/STS)
#pragma unroll
        for (int j = 0; j < 6; j++) {
            int i = h + j * 256;                // < 1536
            int k = i >> 6, vl = i & 63;
            int vg = v0 + vl;
            float wv = (vg < NV) ? lbs_w[vg * KJ + k] : 0.f;
            *(float2*)&sm[S_W2 + i * 2] = make_float2(wv, wv);
        }

        asm volatile("cp.async.wait_group 0;");   // our tables arrived

        // shape blend table: vpsh[coord][bp] = (vt + sd.beta) packed pairs
        {
            int vl = h >> 2;          // 0..63
            int bq = h & 3;           // bp group of 8
            float sdv[3][10];
            float vt3[3];
#pragma unroll
            for (int c = 0; c < 3; c++) {
                vt3[c] = sm[S_VT + vl * 3 + c];
#pragma unroll
                for (int l = 0; l < NBETA; l++)
                    sdv[c][l] = sm[S_SD + vl * 30 + c * 10 + l];
            }
#pragma unroll
            for (int j = 0; j < 8; j++) {
                int bp = bq * 8 + j;
                float b0[10], b1[10];
#pragma unroll
                for (int l = 0; l < NBETA; l++) {
                    b0[l] = sm[S_BET + (2 * bp) * 10 + l];
                    b1[l] = sm[S_BET + (2 * bp + 1) * 10 + l];
                }
#pragma unroll
                for (int c = 0; c < 3; c++) {
                    float s0 = vt3[c], s1 = vt3[c];
#pragma unroll
                    for (int l = 0; l < NBETA; l++) {
                        s0 = fmaf(b0[l], sdv[c][l], s0);
                        s1 = fmaf(b1[l], sdv[c][l], s1);
                    }
                    int coord = vl * 3 + c;
                    *(float2*)&sm[S_VP + (coord * 33 + bp) * 2] =
                        make_float2(s0, s1);
                }
            }
        }
    }
    __syncthreads();   // join: Cs + vpsh + w2 + A2 all visible

    // ==================== epilogue: all 16 warps ====================
    int tn  = tid & 15;      // coord group: coords tn*12..+11
    int tbp = tid >> 4;      // batch pair 0..31
    const float* Cs  = sm;
    const u64*   A2p = (const u64*)&sm[S_A2];
    const u64*   w2p = (const u64*)&sm[S_W2];

    // v_posed packed (b0,b1) per coord = GEMM result + shape table
    u64 xs2[4], ys2[4], zs2[4];
#pragma unroll
    for (int vi = 0; vi < 4; vi++) {
        int vl = tn * 4 + vi;
#pragma unroll
        for (int c = 0; c < 3; c++) {
            int coord = vl * 3 + c;
            u64 cs2 = *(const u64*)&Cs[coord * CS_STRIDE + 2 * tbp];
            u64 sh2 = *(const u64*)&sm[S_VP + (coord * 33 + tbp) * 2];
            u64 vp2 = add2(cs2, sh2);
            if (c == 0) xs2[vi] = vp2;
            else if (c == 1) ys2[vi] = vp2;
            else zs2[vi] = vp2;
        }
    }

    u64 o2[4][3];
#pragma unroll
    for (int vi = 0; vi < 4; vi++) {
        o2[vi][0] = 0ULL; o2[vi][1] = 0ULL; o2[vi][2] = 0ULL;
    }

    for (int k = 0; k < KJ; k++) {
        const u64* Ar = A2p + ((size_t)k * 32 + tbp) * 12;
        u64 r0x = Ar[0], r0y = Ar[1], r0z = Ar[2], r0w = Ar[3];
        u64 r1x = Ar[4], r1y = Ar[5], r1z = Ar[6], r1w = Ar[7];
        u64 r2x = Ar[8], r2y = Ar[9], r2z = Ar[10], r2w = Ar[11];
        const u64* wr = w2p + k * 64 + tn * 4;
#pragma unroll
        for (int vi = 0; vi < 4; vi++) {
            u64 wv = wr[vi];
            u64 tx = ff2(r0x, xs2[vi], ff2(r0y, ys2[vi], ff2(r0z, zs2[vi], r0w)));
            u64 ty = ff2(r1x, xs2[vi], ff2(r1y, ys2[vi], ff2(r1z, zs2[vi], r1w)));
            u64 tz = ff2(r2x, xs2[vi], ff2(r2y, ys2[vi], ff2(r2z, zs2[vi], r2w)));
            o2[vi][0] = ff2(wv, tx, o2[vi][0]);
            o2[vi][1] = ff2(wv, ty, o2[vi][1]);
            o2[vi][2] = ff2(wv, tz, o2[vi][2]);
        }
    }

    // unpack to per-batch coord runs and store (float2, NC even)
    float ov0[12], ov1[12];
#pragma unroll
    for (int vi = 0; vi < 4; vi++)
#pragma unroll
        for (int c = 0; c < 3; c++)
            upk2(o2[vi][c], ov0[vi * 3 + c], ov1[vi * 3 + c]);

    int nbase = n0 + tn * 12;
    size_t base0 = (size_t)(bBase + 2 * tbp) * NC + nbase;
    size_t base1 = base0 + NC;
    if (nbase + 12 <= NC) {
#pragma unroll
        for (int j = 0; j < 6; j++) {
            *(float2*)&out[base0 + 2 * j] = make_float2(ov0[2 * j], ov0[2 * j + 1]);
            *(float2*)&out[base1 + 2 * j] = make_float2(ov1[2 * j], ov1[2 * j + 1]);
        }
    } else {
#pragma unroll
        for (int cj = 0; cj < 12; cj++) {
            if (nbase + cj < NC) {
                out[base0 + cj] = ov0[cj];
                out[base1 + cj] = ov1[cj];
            }
        }
    }
}

// ============================================================================
extern "C" void kernel_launch(void* const* d_in, const int* in_sizes, int n_in,
                              void* d_out, int out_size)
{
    const float* body_pose     = (const float*)d_in[0];
    const float* betas         = (const float*)d_in[1];
    const float* global_orient = (const float*)d_in[2];
    const float* v_template    = (const float*)d_in[3];
    const float* shapedirs     = (const float*)d_in[4];
    const float* posedirs      = (const float*)d_in[5];
    const float* J_regressor   = (const float*)d_in[6];
    const float* lbs_weights   = (const float*)d_in[7];
    const int*   parents       = (const int*)d_in[8];
    float* out = (float*)d_out;

    static bool s_attr = false;
    if (!s_attr) {
        cudaFuncSetAttribute(k3_lbs, cudaFuncAttributeMaxDynamicSharedMemorySize,
                             SMEM_BYTES);
        s_attr = true;
    }

    k1a_jreduce<<<dim3(KJ, 8), 256>>>(J_regressor, v_template, shapedirs);
    k1b_combine<<<1, 256>>>();
    k2_batch<<<BATCH / 8, 256>>>(body_pose, betas, global_orient, parents, out);
    k3_lbs<<<dim3(16, 108), 512, SMEM_BYTES>>>(posedirs, lbs_weights, shapedirs,
                                               v_template, betas, out);
}

// round 8
// speedup vs baseline: 1.1320x; 1.0190x over previous
#include <cuda_runtime.h>
#include <cstdint>

#define BATCH 1024
#define NV 6890
#define KJ 24
#define NBETA 10
#define NPOSE 207
#define NPP 208          // 207 pose rows + 1 zero pad (=13*16)
#define NC 20670         // NV*3
#define NCHUNKS 13
#define NVSEG 864

// ---- scratch (device globals; no allocations allowed) ----
__device__ float g_JT0[KJ * 3];
__device__ float g_JS[KJ * 30];
__device__ float g_part[8 * KJ * 33];
__device__ float g_pfT[NPP * BATCH];      // pose feature^T [p][b], row 207 = 0
__device__ float g_A[BATCH * KJ * 12];    // per batch/joint 3x4 [R|t]

// ---- output layout (concatenated tuple, float32) ----
#define OUT_JT   (BATCH * NV * 3)
#define OUT_J    (OUT_JT + BATCH * KJ * 3)
#define OUT_ROT  (OUT_J + BATCH * KJ * 3)

// ---- cp.async helpers ----
__device__ __forceinline__ void cpa16(uint32_t dst, const void* src, int sb) {
    asm volatile("cp.async.cg.shared.global [%0], [%1], 16, %2;"
                 :: "r"(dst), "l"(src), "r"(sb));
}
__device__ __forceinline__ void cpa8(uint32_t dst, const void* src, int sb) {
    asm volatile("cp.async.ca.shared.global [%0], [%1], 8, %2;"
                 :: "r"(dst), "l"(src), "r"(sb));
}
__device__ __forceinline__ void cpcommit() {
    asm volatile("cp.async.commit_group;");
}
__device__ __forceinline__ uint32_t f2tf32(float x) {
    uint32_t r; asm("cvt.rna.tf32.f32 %0, %1;" : "=r"(r) : "f"(x)); return r;
}

#define MMA_TF32(d, a, b) \
    asm volatile("mma.sync.aligned.m16n8k8.row.col.f32.tf32.tf32.f32 " \
        "{%0,%1,%2,%3}, {%4,%5,%6,%7}, {%8,%9}, {%0,%1,%2,%3};" \
        : "+f"(d[0]), "+f"(d[1]), "+f"(d[2]), "+f"(d[3]) \
        : "r"(a[0]), "r"(a[1]), "r"(a[2]), "r"(a[3]), "r"(b[0]), "r"(b[1]))

// ============================================================================
// Kernel 1a/1b: JT0 = Jreg @ v_template; JS = Jreg . shapedirs (split over V)
// ============================================================================
__global__ void k1a_jreduce(const float* __restrict__ Jreg,
                            const float* __restrict__ vt,
                            const float* __restrict__ sd)
{
    int k = blockIdx.x;
    int seg = blockIdx.y;
    int tid = threadIdx.x;
    int v0 = seg * NVSEG;
    int v1 = min(NV, v0 + NVSEG);
    float acc[33];
#pragma unroll
    for (int e = 0; e < 33; e++) acc[e] = 0.f;

    for (int v = v0 + tid; v < v1; v += 256) {
        float j = Jreg[k * NV + v];
        const float* vp = vt + v * 3;
        acc[0] = fmaf(j, vp[0], acc[0]);
        acc[1] = fmaf(j, vp[1], acc[1]);
        acc[2] = fmaf(j, vp[2], acc[2]);
        const float* sp = sd + v * 30;
#pragma unroll
        for (int e = 0; e < 30; e++) acc[3 + e] = fmaf(j, sp[e], acc[3 + e]);
    }
#pragma unroll
    for (int e = 0; e < 33; e++) {
        for (int off = 16; off; off >>= 1)
            acc[e] += __shfl_down_sync(0xffffffffu, acc[e], off);
    }
    __shared__ float red[8][33];
    int lane = tid & 31, w = tid >> 5;
    if (lane == 0) {
#pragma unroll
        for (int e = 0; e < 33; e++) red[w][e] = acc[e];
    }
    __syncthreads();
    if (tid < 33) {
        float s = 0.f;
#pragma unroll
        for (int w2 = 0; w2 < 8; w2++) s += red[w2][tid];
        g_part[(k * 8 + seg) * 33 + tid] = s;
    }
}

__global__ void k1b_combine()
{
    int idx = threadIdx.x;
    for (; idx < KJ * 33; idx += 256) {
        int k = idx / 33, e = idx % 33;
        float s = 0.f;
#pragma unroll
        for (int seg = 0; seg < 8; seg++) s += g_part[(k * 8 + seg) * 33 + e];
        if (e < 3) g_JT0[k * 3 + e] = s;
        else       g_JS[k * 30 + (e - 3)] = s;
    }
}

// ============================================================================
// Kernel 2: 8 batches/block, one warp per batch. Rodrigues, pose feature,
// joints_t, kinematic chain, A matrices (plain [b][k][12] layout).
// ============================================================================
__global__ __launch_bounds__(256) void k2_batch(
    const float* __restrict__ body_pose,
    const float* __restrict__ betas,
    const float* __restrict__ global_orient,
    const int* __restrict__ parents,
    float* __restrict__ out)
{
    int w = threadIdx.x >> 5;
    int t = threadIdx.x & 31;
    int b = blockIdx.x * 8 + w;
    __shared__ float Rm[8][KJ][9];
    __shared__ float jt[8][KJ][3];
    __shared__ float rel[8][KJ][3];
    __shared__ float ch[8][KJ][12];

    if (t < KJ) {
        float ax, ay, az;
        if (t == 0) {
            ax = global_orient[b * 3 + 0];
            ay = global_orient[b * 3 + 1];
            az = global_orient[b * 3 + 2];
        } else {
            const float* p = body_pose + b * 69 + (t - 1) * 3;
            ax = p[0]; ay = p[1]; az = p[2];
        }
        float ex = ax + 1e-8f, ey = ay + 1e-8f, ez = az + 1e-8f;
        float angle = sqrtf(ex * ex + ey * ey + ez * ez);
        float inv = 1.0f / angle;
        float ux = ax * inv, uy = ay * inv, uz = az * inv;
        float s = sinf(angle), c = cosf(angle);
        float oc = 1.0f - c;
        float uu = ux * ux + uy * uy + uz * uz;
        float r0 = 1.0f + oc * (ux * ux - uu);
        float r1 = -s * uz + oc * (ux * uy);
        float r2 =  s * uy + oc * (ux * uz);
        float r3 =  s * uz + oc * (uy * ux);
        float r4 = 1.0f + oc * (uy * uy - uu);
        float r5 = -s * ux + oc * (uy * uz);
        float r6 = -s * uy + oc * (uz * ux);
        float r7 =  s * ux + oc * (uz * uy);
        float r8 = 1.0f + oc * (uz * uz - uu);
        Rm[w][t][0] = r0; Rm[w][t][1] = r1; Rm[w][t][2] = r2;
        Rm[w][t][3] = r3; Rm[w][t][4] = r4; Rm[w][t][5] = r5;
        Rm[w][t][6] = r6; Rm[w][t][7] = r7; Rm[w][t][8] = r8;

        float* ro = out + OUT_ROT + (size_t)b * 216 + t * 9;
        ro[0] = r0; ro[1] = r1; ro[2] = r2; ro[3] = r3; ro[4] = r4;
        ro[5] = r5; ro[6] = r6; ro[7] = r7; ro[8] = r8;

        if (t >= 1) {
            int p0 = (t - 1) * 9;
            g_pfT[(p0 + 0) * BATCH + b] = r0 - 1.0f;
            g_pfT[(p0 + 1) * BATCH + b] = r1;
            g_pfT[(p0 + 2) * BATCH + b] = r2;
            g_pfT[(p0 + 3) * BATCH + b] = r3;
            g_pfT[(p0 + 4) * BATCH + b] = r4 - 1.0f;
            g_pfT[(p0 + 5) * BATCH + b] = r5;
            g_pfT[(p0 + 6) * BATCH + b] = r6;
            g_pfT[(p0 + 7) * BATCH + b] = r7;
            g_pfT[(p0 + 8) * BATCH + b] = r8 - 1.0f;
        } else {
            g_pfT[207 * BATCH + b] = 0.0f;   // pad row
        }

#pragma unroll
        for (int cc = 0; cc < 3; cc++) {
            float s2 = g_JT0[t * 3 + cc];
#pragma unroll
            for (int l = 0; l < NBETA; l++)
                s2 = fmaf(g_JS[t * 30 + cc * 10 + l], betas[b * 10 + l], s2);
            jt[w][t][cc] = s2;
            out[OUT_JT + (size_t)b * 72 + t * 3 + cc] = s2;
        }
    }
    __syncwarp();
    if (t < KJ) {
        if (t == 0) {
            rel[w][0][0] = jt[w][0][0]; rel[w][0][1] = jt[w][0][1]; rel[w][0][2] = jt[w][0][2];
        } else {
            int p = parents[t];
            rel[w][t][0] = jt[w][t][0] - jt[w][p][0];
            rel[w][t][1] = jt[w][t][1] - jt[w][p][1];
            rel[w][t][2] = jt[w][t][2] - jt[w][p][2];
        }
    }
    __syncwarp();
    if (t < 12) {
        int i = t >> 2, j = t & 3;
        ch[w][0][t] = (j < 3) ? Rm[w][0][i * 3 + j] : rel[w][0][i];
    }
    __syncwarp();
    for (int k = 1; k < KJ; k++) {
        int p = parents[k];
        if (t < 12) {
            int i = t >> 2, j = t & 3;
            float v;
            if (j < 3) {
                v = ch[w][p][i * 4 + 0] * Rm[w][k][0 * 3 + j]
                  + ch[w][p][i * 4 + 1] * Rm[w][k][1 * 3 + j]
                  + ch[w][p][i * 4 + 2] * Rm[w][k][2 * 3 + j];
            } else {
                v = ch[w][p][i * 4 + 0] * rel[w][k][0]
                  + ch[w][p][i * 4 + 1] * rel[w][k][1]
                  + ch[w][p][i * 4 + 2] * rel[w][k][2]
                  + ch[w][p][i * 4 + 3];
            }
            ch[w][k][t] = v;
        }
        __syncwarp();
    }
    if (t < KJ) {
        out[OUT_J + (size_t)b * 72 + t * 3 + 0] = ch[w][t][3];
        out[OUT_J + (size_t)b * 72 + t * 3 + 1] = ch[w][t][7];
        out[OUT_J + (size_t)b * 72 + t * 3 + 2] = ch[w][t][11];
        float* Ao = g_A + ((size_t)b * KJ + t) * 12;
#pragma unroll
        for (int i = 0; i < 3; i++) {
            float tr = ch[w][t][i * 4 + 3]
                     - (ch[w][t][i * 4 + 0] * jt[w][t][0]
                      + ch[w][t][i * 4 + 1] * jt[w][t][1]
                      + ch[w][t][i * 4 + 2] * jt[w][t][2]);
            Ao[i * 4 + 0] = ch[w][t][i * 4 + 0];
            Ao[i * 4 + 1] = ch[w][t][i * 4 + 1];
            Ao[i * 4 + 2] = ch[w][t][i * 4 + 2];
            Ao[i * 4 + 3] = tr;
        }
    }
}

// ============================================================================
// Kernel 3: pose GEMM (tf32 mma, R3 config) + shape blend + tensor-core LBS:
//   T[v, (b,i,j)] = sum_k W[v,k] * A[b,k,i,j]   via 3xTF32 mma (fp32-accurate)
//   out[v,b,i]    = T.xyz . vp + T.w            (4 FMAs)
// 256 threads, 8 warps. Pose warp tile 48x32; T warp tile 16x96, 4 slabs of
// 16 batches. Slab A staged hi/lo; W-frags hoisted to registers.
// ============================================================================
#define SF_STAGE 4352                 // A 16x200=3200 + B 16x72=1152
#define CS_STRIDE 66                  // Csm/vp 192x66 = 12672 (aliases stages)
#define S_SD   17408                  // 64*30 = 1920
#define S_VT   (S_SD + 1920)          // 192
#define S_BET  (S_VT + 192)           // 640
#define S_WH   (S_BET + 640)          // [24][68] = 1632
#define S_WL   (S_WH + 1632)          // 1632
#define S_AH   (S_WL + 1632)          // [24][200] = 4800
#define S_AL   (S_AH + 4800)          // 4800
#define S_T    (S_AL + 4800)          // [64][204] = 13056
#define T_STRIDE 204
#define SMEM_FL (S_T + 13056)         // 46080 floats
#define SMEM_BYTES (SMEM_FL * 4)      // 184320

__device__ __forceinline__ void k3_load_stage(uint32_t smb,
                                              const float* __restrict__ posedirs,
                                              int n0, int kc, int st, int tid)
{
#pragma unroll
    for (int j = 0; j < 6; j++) {
        int i = tid + j * 256;            // < 1536
        int row = i / 96, c2 = i % 96;
        int p = kc * 16 + row;
        int col = n0 + c2 * 2;
        int sb = 0;
        if (p < NPOSE) {
            int rem = NC - col;
            sb = (rem >= 2) ? 8 : 0;
        }
        const float* src = posedirs + (size_t)min(p, NPOSE - 1) * NC
                                    + (sb ? col : 0);
        cpa8(smb + (uint32_t)(st * SF_STAGE + row * 200 + c2 * 2) * 4, src, sb);
    }
    {
        int row = tid / 16, c4 = tid % 16;
        int p = kc * 16 + row;
        int bBase = blockIdx.x * 64;
        cpa16(smb + (uint32_t)(st * SF_STAGE + 3200 + row * 72 + c4 * 4) * 4,
              g_pfT + (size_t)p * BATCH + bBase + c4 * 4, 16);
    }
}

__global__ __launch_bounds__(256, 1) void k3_lbs(
    const float* __restrict__ posedirs,
    const float* __restrict__ lbs_w,
    const float* __restrict__ shapedirs,
    const float* __restrict__ v_template,
    const float* __restrict__ betas,
    float* __restrict__ out)
{
    extern __shared__ float sm[];
    uint32_t smb = (uint32_t)__cvta_generic_to_shared(sm);
    int tid = threadIdx.x;
    int lane = tid & 31, warp = tid >> 5;
    int bBase = blockIdx.x * 64;
    int n0 = blockIdx.y * 192;
    int v0 = n0 / 3;
    int mW = (warp & 3) * 48;
    int nW = (warp >> 2) * 32;

    // ---- epilogue tables via cp.async (own group, waited after GEMM) ----
    {
        int validf = (NV - v0) * 30; if (validf > 1920) validf = 1920;
#pragma unroll
        for (int j = 0; j < 2; j++) {
            int i = tid + j * 256;
            if (i < 480) {
                int fo = i * 4;
                int rem = validf - fo;
                int sb = rem >= 4 ? 16 : (rem > 0 ? rem * 4 : 0);
                cpa16(smb + (uint32_t)(S_SD + fo) * 4,
                      shapedirs + (size_t)v0 * 30 + (sb ? fo : 0), sb);
            }
        }
        if (tid < 48) {
            int fo = tid * 4;
            int validv = (NV - v0) * 3; if (validv > 192) validv = 192;
            int rem = validv - fo;
            int sb = rem >= 4 ? 16 : (rem > 0 ? rem * 4 : 0);
            cpa16(smb + (uint32_t)(S_VT + fo) * 4,
                  v_template + (size_t)v0 * 3 + (sb ? fo : 0), sb);
        }
        if (tid < 160) {
            cpa16(smb + (uint32_t)(S_BET + tid * 4) * 4,
                  betas + (size_t)bBase * 10 + tid * 4, 16);
        }
    }
    cpcommit();

    // ---- prefetch pose GEMM chunks 0, 1 ----
    k3_load_stage(smb, posedirs, n0, 0, 0, tid); cpcommit();
    k3_load_stage(smb, posedirs, n0, 1, 1, tid); cpcommit();

    // ---- W tables (tf32 hi/lo split), k-major [24][68] ----
#pragma unroll
    for (int j = 0; j < 6; j++) {
        int i = tid + j * 256;               // < 1536
        int k = i >> 6, vl = i & 63;
        int vg = v0 + vl;
        float wv = (vg < NV) ? lbs_w[vg * KJ + k] : 0.f;
        uint32_t hb = f2tf32(wv);
        float hf = __uint_as_float(hb);
        sm[S_WH + k * 68 + vl] = hf;
        sm[S_WL + k * 68 + vl] = wv - hf;
    }

    // ---- pose GEMM (tf32, 48x32 warp tiles) ----
    float acc[3][4][4];
#pragma unroll
    for (int it = 0; it < 3; it++)
#pragma unroll
        for (int jt = 0; jt < 4; jt++)
#pragma unroll
            for (int e = 0; e < 4; e++) acc[it][jt][e] = 0.f;

    for (int kc = 0; kc < NCHUNKS; kc++) {
        if (kc + 2 < NCHUNKS)
            k3_load_stage(smb, posedirs, n0, kc + 2, (kc + 2) & 3, tid);
        cpcommit();
        asm volatile("cp.async.wait_group 2;");
        __syncthreads();

        const float* As = sm + (kc & 3) * SF_STAGE;
        const float* Bs = As + 3200;
#pragma unroll
        for (int kk = 0; kk < 2; kk++) {
            int k0 = kk * 8;
            uint32_t a[3][4], b[4][2];
            int ar0 = (k0 + (lane & 3)) * 200 + mW + (lane >> 2);
            int ar1 = ar0 + 4 * 200;
#pragma unroll
            for (int it = 0; it < 3; it++) {
                a[it][0] = __float_as_uint(As[ar0 + it * 16]);
                a[it][1] = __float_as_uint(As[ar0 + it * 16 + 8]);
                a[it][2] = __float_as_uint(As[ar1 + it * 16]);
                a[it][3] = __float_as_uint(As[ar1 + it * 16 + 8]);
            }
            int br0 = (k0 + (lane & 3)) * 72 + nW + (lane >> 2);
            int br1 = br0 + 4 * 72;
#pragma unroll
            for (int jt = 0; jt < 4; jt++) {
                b[jt][0] = __float_as_uint(Bs[br0 + jt * 8]);
                b[jt][1] = __float_as_uint(Bs[br1 + jt * 8]);
            }
#pragma unroll
            for (int it = 0; it < 3; it++)
#pragma unroll
                for (int jt = 0; jt < 4; jt++)
                    MMA_TF32(acc[it][jt], a[it], b[jt]);
        }
    }
    __syncthreads();   // all stage reads done; Csm may overwrite stages

    // ---- dump pose accumulators to Csm (stride 66) ----
#pragma unroll
    for (int it = 0; it < 3; it++)
#pragma unroll
        for (int jt = 0; jt < 4; jt++) {
            int m = mW + it * 16 + (lane >> 2);
            int n = nW + jt * 8 + 2 * (lane & 3);
            sm[m * CS_STRIDE + n]           = acc[it][jt][0];
            sm[m * CS_STRIDE + n + 1]       = acc[it][jt][1];
            sm[(m + 8) * CS_STRIDE + n]     = acc[it][jt][2];
            sm[(m + 8) * CS_STRIDE + n + 1] = acc[it][jt][3];
        }
    asm volatile("cp.async.wait_group 0;");   // tables arrived
    __syncthreads();

    // ---- shape blend in place: vp[coord][b] = Cpose + vt + sd.beta ----
    {
        int v = tid >> 2;                // 0..63
        int bq = (tid & 3) * 16;
        float vt3[3], sdv[3][10];
#pragma unroll
        for (int c = 0; c < 3; c++) {
            vt3[c] = sm[S_VT + v * 3 + c];
#pragma unroll
            for (int l = 0; l < NBETA; l++)
                sdv[c][l] = sm[S_SD + v * 30 + c * 10 + l];
        }
        for (int bb = 0; bb < 16; bb++) {
            int b = bq + bb;
            float be[10];
#pragma unroll
            for (int l = 0; l < NBETA; l++) be[l] = sm[S_BET + b * 10 + l];
#pragma unroll
            for (int c = 0; c < 3; c++) {
                float s = vt3[c];
#pragma unroll
                for (int l = 0; l < NBETA; l++) s = fmaf(be[l], sdv[c][l], s);
                sm[(3 * v + c) * CS_STRIDE + b] += s;
            }
        }
    }
    __syncthreads();   // vp final, W tables long since visible

    // ---- hoist W fragments (reused across all 4 slabs) ----
    int mT = (warp & 3) * 16;
    int nT = (warp >> 2) * 96;
    uint32_t awh[3][4], awl[3][4];
#pragma unroll
    for (int kc = 0; kc < 3; kc++) {
        int kb = kc * 8 + (lane & 3);
        int mr = mT + (lane >> 2);
        awh[kc][0] = __float_as_uint(sm[S_WH + kb * 68 + mr]);
        awh[kc][1] = __float_as_uint(sm[S_WH + kb * 68 + mr + 8]);
        awh[kc][2] = __float_as_uint(sm[S_WH + (kb + 4) * 68 + mr]);
        awh[kc][3] = __float_as_uint(sm[S_WH + (kb + 4) * 68 + mr + 8]);
        awl[kc][0] = __float_as_uint(sm[S_WL + kb * 68 + mr]);
        awl[kc][1] = __float_as_uint(sm[S_WL + kb * 68 + mr + 8]);
        awl[kc][2] = __float_as_uint(sm[S_WL + (kb + 4) * 68 + mr]);
        awl[kc][3] = __float_as_uint(sm[S_WL + (kb + 4) * 68 + mr + 8]);
    }

    // ---- 4 slabs of 16 batches ----
    for (int sb = 0; sb < 4; sb++) {
        int b0 = bBase + sb * 16;

        // stage A slab hi/lo: A_slab[k][bl*12 + e], stride 200
#pragma unroll
        for (int r = 0; r < 5; r++) {
            int i = tid + r * 256;
            if (i < 1152) {                       // 16 b x 72 float4
                const float4* src = (const float4*)(g_A + (size_t)b0 * 288) + i;
                float4 q = *src;
                int bl = i / 72, rem = i % 72;
                int k = rem / 3, e4 = rem % 3;
                int nn = bl * 12 + e4 * 4;
                uint32_t h0 = f2tf32(q.x), h1 = f2tf32(q.y),
                         h2 = f2tf32(q.z), h3 = f2tf32(q.w);
                float f0 = __uint_as_float(h0), f1 = __uint_as_float(h1),
                      f2 = __uint_as_float(h2), f3 = __uint_as_float(h3);
                *(float4*)&sm[S_AH + k * 200 + nn] = make_float4(f0, f1, f2, f3);
                *(float4*)&sm[S_AL + k * 200 + nn] =
                    make_float4(q.x - f0, q.y - f1, q.z - f2, q.w - f3);
            }
        }
        __syncthreads();

        // T-GEMM: M=64 (v), N=192 (bl*12+e), K=24, 3xTF32
        {
            float c[12][4];
#pragma unroll
            for (int nf = 0; nf < 12; nf++)
#pragma unroll
                for (int e = 0; e < 4; e++) c[nf][e] = 0.f;

#pragma unroll
            for (int kc = 0; kc < 3; kc++) {
                int kb = (kc * 8 + (lane & 3)) * 200 + nT + (lane >> 2);
#pragma unroll
                for (int nf = 0; nf < 12; nf++) {
                    uint32_t bh[2], bl_[2];
                    int bi = kb + nf * 8;
                    bh[0]  = __float_as_uint(sm[S_AH + bi]);
                    bh[1]  = __float_as_uint(sm[S_AH + bi + 4 * 200]);
                    bl_[0] = __float_as_uint(sm[S_AL + bi]);
                    bl_[1] = __float_as_uint(sm[S_AL + bi + 4 * 200]);
                    MMA_TF32(c[nf], awh[kc], bh);
                    MMA_TF32(c[nf], awh[kc], bl_);
                    MMA_TF32(c[nf], awl[kc], bh);
                }
            }
            // dump T
#pragma unroll
            for (int nf = 0; nf < 12; nf++) {
                int m = mT + (lane >> 2);
                int n = nT + nf * 8 + 2 * (lane & 3);
                sm[S_T + m * T_STRIDE + n]           = c[nf][0];
                sm[S_T + m * T_STRIDE + n + 1]       = c[nf][1];
                sm[S_T + (m + 8) * T_STRIDE + n]     = c[nf][2];
                sm[S_T + (m + 8) * T_STRIDE + n + 1] = c[nf][3];
            }
        }
        __syncthreads();

        // apply: out[b, n0 + 3v + i] = T.xyz . vp + T.w
        if (tid < 192) {
            int v = tid / 3, i = tid % 3;
            int nco = n0 + tid;
            bool ok = (nco < NC);
            for (int bb = 0; bb < 16; bb++) {
                float4 t4 = *(const float4*)&sm[S_T + v * T_STRIDE + bb * 12 + i * 4];
                int bl = sb * 16 + bb;
                float vp0 = sm[(3 * v + 0) * CS_STRIDE + bl];
                float vp1 = sm[(3 * v + 1) * CS_STRIDE + bl];
                float vp2 = sm[(3 * v + 2) * CS_STRIDE + bl];
                float o = fmaf(t4.x, vp0, fmaf(t4.y, vp1, fmaf(t4.z, vp2, t4.w)));
                if (ok) out[(size_t)(b0 + bb) * NC + nco] = o;
            }
        }
        __syncthreads();   // T/A_slab reusable next slab
    }
}

// ============================================================================
extern "C" void kernel_launch(void* const* d_in, const int* in_sizes, int n_in,
                              void* d_out, int out_size)
{
    const float* body_pose     = (const float*)d_in[0];
    const float* betas         = (const float*)d_in[1];
    const float* global_orient = (const float*)d_in[2];
    const float* v_template    = (const float*)d_in[3];
    const float* shapedirs     = (const float*)d_in[4];
    const float* posedirs      = (const float*)d_in[5];
    const float* J_regressor   = (const float*)d_in[6];
    const float* lbs_weights   = (const float*)d_in[7];
    const int*   parents       = (const int*)d_in[8];
    float* out = (float*)d_out;

    static bool s_attr = false;
    if (!s_attr) {
        cudaFuncSetAttribute(k3_lbs, cudaFuncAttributeMaxDynamicSharedMemorySize,
                             SMEM_BYTES);
        s_attr = true;
    }

    k1a_jreduce<<<dim3(KJ, 8), 256>>>(J_regressor, v_template, shapedirs);
    k1b_combine<<<1, 256>>>();
    k2_batch<<<BATCH / 8, 256>>>(body_pose, betas, global_orient, parents, out);
    k3_lbs<<<dim3(16, 108), 256, SMEM_BYTES>>>(posedirs, lbs_weights, shapedirs,
                                               v_template, betas, out);
}